// round 10
// baseline (speedup 1.0000x reference)
#include <cuda_runtime.h>
#include <math.h>
#include <stdint.h>

static constexpr int B_ = 8;
static constexpr int C_ = 256;
static constexpr int N_ = 2048;
static constexpr int M_ = 2048;

// Scratch (no cudaMalloc allowed)
__device__ float g_q[B_*C_*N_];
__device__ float g_k[B_*C_*M_];
__device__ float g_v[B_*C_*M_];
__device__ float g_attn[B_*C_*N_];
__device__ float g_mo[B_*C_*N_];
__device__ float g_h[B_*2*C_*N_];

// ---------------------------------------------------------------------------
// tf32 helpers
// ---------------------------------------------------------------------------
__device__ __forceinline__ uint32_t f2tf32(float f) {
    uint32_t r;
    asm("cvt.rna.tf32.f32 %0, %1;" : "=r"(r) : "f"(f));
    return r;
}

__device__ __forceinline__ void mma_tf32(
    float d[4], const uint32_t a[4], uint32_t b0, uint32_t b1, const float c[4])
{
    asm volatile(
        "mma.sync.aligned.m16n8k8.row.col.f32.tf32.tf32.f32 "
        "{%0,%1,%2,%3}, {%4,%5,%6,%7}, {%8,%9}, {%10,%11,%12,%13};"
        : "=f"(d[0]), "=f"(d[1]), "=f"(d[2]), "=f"(d[3])
        : "r"(a[0]), "r"(a[1]), "r"(a[2]), "r"(a[3]),
          "r"(b0), "r"(b1),
          "f"(c[0]), "f"(c[1]), "f"(c[2]), "f"(c[3]));
}

// ---------------------------------------------------------------------------
// Tensor-core GEMM with fused epilogue.
// Y[b][o][n] = epi( sum_i W[o][i] * X[b][i][n] + bias[o] )
// Channel i < Ca from Xa, else Xb (concat).
// MODE 0: +bias
// MODE 1: (+bias) * e0[b][n]               (weight_v)
// MODE 2: relu((+bias)*inv[o] + add[o])    (BN)
// MODE 3: (+bias) + e0[b][o][n]            (residual)
// CTA: 128 threads / 4 warps; tile 64 o x 128 n; K-chunk 32.
// Warp w owns o-rows [16w, 16w+16); all 128 n.
// Ws[k][o] stride 70 (A-frag loads conflict-free), Xs[k][n] stride 132.
// ---------------------------------------------------------------------------
static constexpr int WS_ST = 70;
static constexpr int XS_ST = 132;

template<int MODE>
__global__ void __launch_bounds__(128, 4) gemm_mma(
    const float* __restrict__ W, const float* __restrict__ bias,
    const float* __restrict__ Xa, const float* __restrict__ Xb,
    float* __restrict__ Y, int Cout, int Cin, int Ca,
    const float* __restrict__ e0, const float* __restrict__ e1,
    const float* __restrict__ e2, const float* __restrict__ e3)
{
    __shared__ float Ws[32 * WS_ST];
    __shared__ float Xs[32 * XS_ST];

    const int b  = blockIdx.z;
    const int o0 = blockIdx.y * 64;
    const int n0 = blockIdx.x * 128;
    const int t  = threadIdx.x;
    const int lane = t & 31, w = t >> 5;
    const int g = lane >> 2, q4 = lane & 3;
    const int ow = w * 16;
    const int Cb = Cin - Ca;

    // W-load assignment: o = t&63 (lanes of a warp span 32 consecutive rows,
    // so scatter STS banks are o+const -> conflict-free), iq0 = (t>>6)*16.
    const int wlo  = t & 63;
    const int wiq0 = (t >> 6) * 16;

    float acc[16][4];
    #pragma unroll
    for (int nc = 0; nc < 16; nc++)
        #pragma unroll
        for (int j = 0; j < 4; j++) acc[nc][j] = 0.f;

    for (int i0 = 0; i0 < Cin; i0 += 32) {
        __syncthreads();   // prior chunk's fragment reads done
        // ---- Load W tile [64 o][32 k], store transposed Ws[k][o] (tf32) ----
        #pragma unroll
        for (int j = 0; j < 4; j++) {
            const int kk = wiq0 + 4*j;
            float4 w4 = *(const float4*)&W[(size_t)(o0 + wlo) * Cin + i0 + kk];
            Ws[(kk+0)*WS_ST + wlo] = __uint_as_float(f2tf32(w4.x));
            Ws[(kk+1)*WS_ST + wlo] = __uint_as_float(f2tf32(w4.y));
            Ws[(kk+2)*WS_ST + wlo] = __uint_as_float(f2tf32(w4.z));
            Ws[(kk+3)*WS_ST + wlo] = __uint_as_float(f2tf32(w4.w));
        }
        // ---- Load X tile [32 k][128 n] (tf32) ----
        #pragma unroll
        for (int r = 0; r < 8; r++) {
            int lin = r*128 + t;
            int i = lin >> 5, n4 = (lin & 31) << 2;
            int ig = i0 + i;
            float4 xv;
            if (ig < Ca) xv = *(const float4*)&Xa[((size_t)b*Ca + ig) * N_ + n0 + n4];
            else         xv = *(const float4*)&Xb[((size_t)b*Cb + (ig - Ca)) * N_ + n0 + n4];
            float* dst = &Xs[i*XS_ST + n4];
            dst[0] = __uint_as_float(f2tf32(xv.x));
            dst[1] = __uint_as_float(f2tf32(xv.y));
            dst[2] = __uint_as_float(f2tf32(xv.z));
            dst[3] = __uint_as_float(f2tf32(xv.w));
        }
        __syncthreads();

        // ---- 4 sub-chunks of k=8: A from Ws, B from Xs, 16 mmas each ----
        #pragma unroll
        for (int s = 0; s < 4; s++) {
            uint32_t a[4];
            const float* wr0 = &Ws[(8*s + q4    )*WS_ST + ow];
            const float* wr1 = &Ws[(8*s + q4 + 4)*WS_ST + ow];
            a[0] = __float_as_uint(wr0[g]);
            a[1] = __float_as_uint(wr0[g + 8]);
            a[2] = __float_as_uint(wr1[g]);
            a[3] = __float_as_uint(wr1[g + 8]);
            const float* x0 = &Xs[(8*s + q4    )*XS_ST + g];
            const float* x1 = &Xs[(8*s + q4 + 4)*XS_ST + g];
            #pragma unroll
            for (int nc = 0; nc < 16; nc++) {
                uint32_t b0 = __float_as_uint(x0[8*nc]);
                uint32_t b1 = __float_as_uint(x1[8*nc]);
                mma_tf32(acc[nc], a, b0, b1, acc[nc]);
            }
        }
    }

    // ---- Epilogue ----
    const int row0 = o0 + ow + g;
    const int row1 = row0 + 8;
    const float bi0 = bias[row0];
    const float bi1 = bias[row1];
    float inv0, add0, inv1, add1;
    if constexpr (MODE == 2) {
        inv0 = e0[row0] * rsqrtf(e3[row0] + 1e-5f);
        add0 = e1[row0] - e2[row0] * inv0;
        inv1 = e0[row1] * rsqrtf(e3[row1] + 1e-5f);
        add1 = e1[row1] - e2[row1] * inv1;
    }
    const size_t yb0 = ((size_t)b*Cout + row0) * N_;
    const size_t yb1 = ((size_t)b*Cout + row1) * N_;

    #pragma unroll
    for (int nc = 0; nc < 16; nc++) {
        const int n = n0 + 8*nc + 2*q4;
        float2 y0 = make_float2(acc[nc][0] + bi0, acc[nc][1] + bi0);
        float2 y1 = make_float2(acc[nc][2] + bi1, acc[nc][3] + bi1);
        if constexpr (MODE == 1) {
            float2 wv2 = *(const float2*)&e0[(size_t)b * N_ + n];
            y0.x *= wv2.x; y0.y *= wv2.y;
            y1.x *= wv2.x; y1.y *= wv2.y;
        }
        if constexpr (MODE == 2) {
            y0.x = fmaxf(fmaf(y0.x, inv0, add0), 0.f);
            y0.y = fmaxf(fmaf(y0.y, inv0, add0), 0.f);
            y1.x = fmaxf(fmaf(y1.x, inv1, add1), 0.f);
            y1.y = fmaxf(fmaf(y1.y, inv1, add1), 0.f);
        }
        if constexpr (MODE == 3) {
            float2 r0 = *(const float2*)&e0[yb0 + n];
            float2 r1 = *(const float2*)&e0[yb1 + n];
            y0.x += r0.x; y0.y += r0.y;
            y1.x += r1.x; y1.y += r1.y;
        }
        *(float2*)&Y[yb0 + n] = y0;
        *(float2*)&Y[yb1 + n] = y1;
    }
}

// ---------------------------------------------------------------------------
// Attention via mma.sync tf32 (unchanged from R8 — passed at 330us).
// ---------------------------------------------------------------------------
static constexpr int ST = 72;
static constexpr int TILE_F = 64 * ST;

__global__ void __launch_bounds__(128) attn_mma(
    const float* __restrict__ Q, const float* __restrict__ K,
    const float* __restrict__ V, float* __restrict__ O)
{
    extern __shared__ float sm[];
    float* Ks = sm;
    float* Vs = sm + TILE_F;
    float* Ps = sm + 2*TILE_F;

    const int bh = blockIdx.y;
    const int n0 = blockIdx.x * 64;
    const size_t base = (size_t)bh * 64 * 2048;
    const int t = threadIdx.x;
    const int lane = t & 31, w = t >> 5;
    const int g = lane >> 2, q4 = lane & 3;
    const int nw = w * 16;

    #pragma unroll
    for (int it = 0; it < 8; it++) {
        int lin = it*128 + t;
        int d = lin >> 4, n4 = (lin & 15) << 2;
        float4 qv = *(const float4*)&Q[base + (size_t)d * 2048 + n0 + n4];
        float* dst = &Ps[d*ST + n4];
        dst[0] = __uint_as_float(f2tf32(qv.x));
        dst[1] = __uint_as_float(f2tf32(qv.y));
        dst[2] = __uint_as_float(f2tf32(qv.z));
        dst[3] = __uint_as_float(f2tf32(qv.w));
    }
    __syncthreads();

    uint32_t qa[8][4];
    #pragma unroll
    for (int dc = 0; dc < 8; dc++) {
        qa[dc][0] = __float_as_uint(Ps[(8*dc + q4    )*ST + nw + g    ]);
        qa[dc][1] = __float_as_uint(Ps[(8*dc + q4    )*ST + nw + g + 8]);
        qa[dc][2] = __float_as_uint(Ps[(8*dc + q4 + 4)*ST + nw + g    ]);
        qa[dc][3] = __float_as_uint(Ps[(8*dc + q4 + 4)*ST + nw + g + 8]);
    }

    float o_[8][4];
    #pragma unroll
    for (int dc = 0; dc < 8; dc++)
        #pragma unroll
        for (int j = 0; j < 4; j++) o_[dc][j] = 0.f;
    float l0 = 0.f, l1 = 0.f;

    float* Pw = Ps + w * 16 * ST;

    for (int m0 = 0; m0 < M_; m0 += 64) {
        __syncthreads();
        #pragma unroll
        for (int it = 0; it < 8; it++) {
            int lin = it*128 + t;
            int d = lin >> 4, m4 = (lin & 15) << 2;
            const size_t goff = base + (size_t)d * 2048 + m0 + m4;
            float4 kv = *(const float4*)&K[goff];
            float4 vv = *(const float4*)&V[goff];
            float* kd = &Ks[d*ST + m4];
            float* vd = &Vs[d*ST + m4];
            kd[0] = __uint_as_float(f2tf32(kv.x));
            kd[1] = __uint_as_float(f2tf32(kv.y));
            kd[2] = __uint_as_float(f2tf32(kv.z));
            kd[3] = __uint_as_float(f2tf32(kv.w));
            vd[0] = __uint_as_float(f2tf32(vv.x));
            vd[1] = __uint_as_float(f2tf32(vv.y));
            vd[2] = __uint_as_float(f2tf32(vv.z));
            vd[3] = __uint_as_float(f2tf32(vv.w));
        }
        __syncthreads();

        float s[8][4];
        #pragma unroll
        for (int mc = 0; mc < 8; mc++)
            #pragma unroll
            for (int j = 0; j < 4; j++) s[mc][j] = 0.f;

        #pragma unroll
        for (int dc = 0; dc < 8; dc++) {
            const float* r0 = &Ks[(8*dc + q4    )*ST + g];
            const float* r1 = &Ks[(8*dc + q4 + 4)*ST + g];
            #pragma unroll
            for (int mc = 0; mc < 8; mc++) {
                uint32_t b0 = __float_as_uint(r0[8*mc]);
                uint32_t b1 = __float_as_uint(r1[8*mc]);
                mma_tf32(s[mc], qa[dc], b0, b1, s[mc]);
            }
        }

        #pragma unroll
        for (int mc = 0; mc < 8; mc++) {
            float e0 = __expf(s[mc][0] * 0.125f);
            float e1 = __expf(s[mc][1] * 0.125f);
            float e2 = __expf(s[mc][2] * 0.125f);
            float e3 = __expf(s[mc][3] * 0.125f);
            l0 += e0 + e1;
            l1 += e2 + e3;
            float2 p01 = make_float2(__uint_as_float(f2tf32(e0)), __uint_as_float(f2tf32(e1)));
            float2 p23 = make_float2(__uint_as_float(f2tf32(e2)), __uint_as_float(f2tf32(e3)));
            *(float2*)&Pw[(g    )*ST + 8*mc + 2*q4] = p01;
            *(float2*)&Pw[(g + 8)*ST + 8*mc + 2*q4] = p23;
        }
        __syncwarp();

        #pragma unroll
        for (int mc = 0; mc < 8; mc++) {
            uint32_t pa[4];
            pa[0] = __float_as_uint(Pw[(g    )*ST + 8*mc + q4    ]);
            pa[1] = __float_as_uint(Pw[(g + 8)*ST + 8*mc + q4    ]);
            pa[2] = __float_as_uint(Pw[(g    )*ST + 8*mc + q4 + 4]);
            pa[3] = __float_as_uint(Pw[(g + 8)*ST + 8*mc + q4 + 4]);
            #pragma unroll
            for (int dc = 0; dc < 8; dc++) {
                const float* vr = &Vs[(8*dc + g)*ST + 8*mc];
                uint32_t b0 = __float_as_uint(vr[q4    ]);
                uint32_t b1 = __float_as_uint(vr[q4 + 4]);
                mma_tf32(o_[dc], pa, b0, b1, o_[dc]);
            }
        }
    }

    l0 += __shfl_xor_sync(0xffffffffu, l0, 1);
    l0 += __shfl_xor_sync(0xffffffffu, l0, 2);
    l1 += __shfl_xor_sync(0xffffffffu, l1, 1);
    l1 += __shfl_xor_sync(0xffffffffu, l1, 2);
    const float inv0 = 1.0f / l0;
    const float inv1 = 1.0f / l1;

    __syncthreads();
    #pragma unroll
    for (int dc = 0; dc < 8; dc++) {
        #pragma unroll
        for (int j = 0; j < 2; j++) {
            int d = 8*dc + 2*q4 + j;
            Ks[d*ST + nw + g    ] = o_[dc][j]     * inv0;
            Ks[d*ST + nw + g + 8] = o_[dc][2 + j] * inv1;
        }
    }
    __syncthreads();
    #pragma unroll
    for (int it = 0; it < 32; it++) {
        int lin = it*128 + t;
        int n = lin & 63, d = lin >> 6;
        O[base + (size_t)d * 2048 + n0 + n] = Ks[d*ST + n];
    }
}

// ---------------------------------------------------------------------------
extern "C" void kernel_launch(void* const* d_in, const int* in_sizes, int n_in,
                              void* d_out, int out_size)
{
    const float* desc1 = (const float*)d_in[0];
    const float* desc2 = (const float*)d_in[1];
    const float* wv    = (const float*)d_in[2];
    const float* Wq    = (const float*)d_in[3];
    const float* bq    = (const float*)d_in[4];
    const float* Wk    = (const float*)d_in[5];
    const float* bk    = (const float*)d_in[6];
    const float* Wv    = (const float*)d_in[7];
    const float* bv    = (const float*)d_in[8];
    const float* Wm    = (const float*)d_in[9];
    const float* bm    = (const float*)d_in[10];
    const float* Wc1   = (const float*)d_in[11];
    const float* bc1   = (const float*)d_in[12];
    const float* gamma = (const float*)d_in[13];
    const float* beta  = (const float*)d_in[14];
    const float* mean  = (const float*)d_in[15];
    const float* var   = (const float*)d_in[16];
    const float* Wc2   = (const float*)d_in[17];
    const float* bc2   = (const float*)d_in[18];
    float* out = (float*)d_out;

    float *q, *k, *v, *attn, *mo, *h;
    cudaGetSymbolAddress((void**)&q,    g_q);
    cudaGetSymbolAddress((void**)&k,    g_k);
    cudaGetSymbolAddress((void**)&v,    g_v);
    cudaGetSymbolAddress((void**)&attn, g_attn);
    cudaGetSymbolAddress((void**)&mo,   g_mo);
    cudaGetSymbolAddress((void**)&h,    g_h);

    const dim3 blk(128);
    const dim3 gp(N_/128, C_/64, B_);    // 16 x 4 x 8
    const dim3 gh(N_/128, 2*C_/64, B_);  // 16 x 8 x 8

    gemm_mma<0><<<gp, blk>>>(Wq, bq, desc1, nullptr, q, C_, C_, C_,
                             nullptr, nullptr, nullptr, nullptr);
    gemm_mma<0><<<gp, blk>>>(Wk, bk, desc2, nullptr, k, C_, C_, C_,
                             nullptr, nullptr, nullptr, nullptr);
    gemm_mma<1><<<gp, blk>>>(Wv, bv, desc2, nullptr, v, C_, C_, C_,
                             wv, nullptr, nullptr, nullptr);

    const int smem_bytes = 3 * TILE_F * sizeof(float);
    cudaFuncSetAttribute(attn_mma, cudaFuncAttributeMaxDynamicSharedMemorySize, smem_bytes);
    attn_mma<<<dim3(N_/64, B_*4), 128, smem_bytes>>>(q, k, v, attn);

    gemm_mma<0><<<gp, blk>>>(Wm, bm, attn, nullptr, mo, C_, C_, C_,
                             nullptr, nullptr, nullptr, nullptr);

    gemm_mma<2><<<gh, blk>>>(Wc1, bc1, desc1, mo, h, 2*C_, 2*C_, C_,
                             gamma, beta, mean, var);

    gemm_mma<3><<<gp, blk>>>(Wc2, bc2, h, nullptr, out, C_, 2*C_, 2*C_,
                             desc1, nullptr, nullptr, nullptr);
}

// round 11
// speedup vs baseline: 1.4725x; 1.4725x over previous
#include <cuda_runtime.h>
#include <cuda_bf16.h>
#include <math.h>
#include <stdint.h>

static constexpr int B_ = 8;
static constexpr int C_ = 256;
static constexpr int N_ = 2048;
static constexpr int M_ = 2048;

// Scratch (no cudaMalloc allowed)
__device__ float g_q[B_*C_*N_];
__device__ float g_k[B_*C_*M_];
__device__ float g_v[B_*C_*M_];
__device__ float g_attn[B_*C_*N_];
__device__ float g_mo[B_*C_*N_];
__device__ float g_h[B_*2*C_*N_];

// ---------------------------------------------------------------------------
// helpers
// ---------------------------------------------------------------------------
__device__ __forceinline__ uint32_t f2tf32(float f) {
    uint32_t r;
    asm("cvt.rna.tf32.f32 %0, %1;" : "=r"(r) : "f"(f));
    return r;
}

__device__ __forceinline__ void mma_tf32(
    float d[4], const uint32_t a[4], uint32_t b0, uint32_t b1, const float c[4])
{
    asm volatile(
        "mma.sync.aligned.m16n8k8.row.col.f32.tf32.tf32.f32 "
        "{%0,%1,%2,%3}, {%4,%5,%6,%7}, {%8,%9}, {%10,%11,%12,%13};"
        : "=f"(d[0]), "=f"(d[1]), "=f"(d[2]), "=f"(d[3])
        : "r"(a[0]), "r"(a[1]), "r"(a[2]), "r"(a[3]),
          "r"(b0), "r"(b1),
          "f"(c[0]), "f"(c[1]), "f"(c[2]), "f"(c[3]));
}

__device__ __forceinline__ void mma_bf16(
    float d[4], const uint32_t a[4], uint32_t b0, uint32_t b1, const float c[4])
{
    asm volatile(
        "mma.sync.aligned.m16n8k16.row.col.f32.bf16.bf16.f32 "
        "{%0,%1,%2,%3}, {%4,%5,%6,%7}, {%8,%9}, {%10,%11,%12,%13};"
        : "=f"(d[0]), "=f"(d[1]), "=f"(d[2]), "=f"(d[3])
        : "r"(a[0]), "r"(a[1]), "r"(a[2]), "r"(a[3]),
          "r"(b0), "r"(b1),
          "f"(c[0]), "f"(c[1]), "f"(c[2]), "f"(c[3]));
}

__device__ __forceinline__ uint32_t pkbf(float lo, float hi) {
    __nv_bfloat162 h = __floats2bfloat162_rn(lo, hi);
    return *(uint32_t*)&h;
}

// ---------------------------------------------------------------------------
// Tensor-core GEMM with fused epilogue (tf32).
// CTA: 128 thr / 4 warps; tile 64 o x 128 n; K-chunk 32.
// Warp (w&1) picks o-half (32 rows = 2 strips), (w>>1) picks n-half (64).
// Strides: Ws 72 (banks 8*q4+g), Xs 136 (banks 8*q4+g) — conflict-free.
// MODE 0:+bias 1:*weight_v 2:BN+ReLU 3:+residual
// ---------------------------------------------------------------------------
static constexpr int WS_ST = 72;
static constexpr int XS_ST = 136;

template<int MODE>
__global__ void __launch_bounds__(128, 4) gemm_mma(
    const float* __restrict__ W, const float* __restrict__ bias,
    const float* __restrict__ Xa, const float* __restrict__ Xb,
    float* __restrict__ Y, int Cout, int Cin, int Ca,
    const float* __restrict__ e0, const float* __restrict__ e1,
    const float* __restrict__ e2, const float* __restrict__ e3)
{
    __shared__ float Ws[32 * WS_ST];
    __shared__ float Xs[32 * XS_ST];

    const int b  = blockIdx.z;
    const int o0 = blockIdx.y * 64;
    const int n0 = blockIdx.x * 128;
    const int t  = threadIdx.x;
    const int lane = t & 31, w = t >> 5;
    const int g = lane >> 2, q4 = lane & 3;
    const int ow = (w & 1) * 32;         // o-half (2 strips of 16)
    const int nwp = (w >> 1) * 64;       // n-half
    const int Cb = Cin - Ca;

    const int wlo  = t & 63;
    const int wiq0 = (t >> 6) * 16;

    float acc[2][8][4];
    #pragma unroll
    for (int st = 0; st < 2; st++)
        #pragma unroll
        for (int nc = 0; nc < 8; nc++)
            #pragma unroll
            for (int j = 0; j < 4; j++) acc[st][nc][j] = 0.f;

    for (int i0 = 0; i0 < Cin; i0 += 32) {
        __syncthreads();
        // ---- W tile [64 o][32 k] -> Ws[k][o] (tf32) ----
        #pragma unroll
        for (int j = 0; j < 4; j++) {
            const int kk = wiq0 + 4*j;
            float4 w4 = *(const float4*)&W[(size_t)(o0 + wlo) * Cin + i0 + kk];
            Ws[(kk+0)*WS_ST + wlo] = __uint_as_float(f2tf32(w4.x));
            Ws[(kk+1)*WS_ST + wlo] = __uint_as_float(f2tf32(w4.y));
            Ws[(kk+2)*WS_ST + wlo] = __uint_as_float(f2tf32(w4.z));
            Ws[(kk+3)*WS_ST + wlo] = __uint_as_float(f2tf32(w4.w));
        }
        // ---- X tile [32 k][128 n] (tf32) ----
        #pragma unroll
        for (int r = 0; r < 8; r++) {
            int lin = r*128 + t;
            int i = lin >> 5, n4 = (lin & 31) << 2;
            int ig = i0 + i;
            float4 xv;
            if (ig < Ca) xv = *(const float4*)&Xa[((size_t)b*Ca + ig) * N_ + n0 + n4];
            else         xv = *(const float4*)&Xb[((size_t)b*Cb + (ig - Ca)) * N_ + n0 + n4];
            float* dst = &Xs[i*XS_ST + n4];
            dst[0] = __uint_as_float(f2tf32(xv.x));
            dst[1] = __uint_as_float(f2tf32(xv.y));
            dst[2] = __uint_as_float(f2tf32(xv.z));
            dst[3] = __uint_as_float(f2tf32(xv.w));
        }
        __syncthreads();

        #pragma unroll
        for (int s = 0; s < 4; s++) {
            uint32_t a2r[2][4];
            #pragma unroll
            for (int st = 0; st < 2; st++) {
                const float* wr0 = &Ws[(8*s + q4    )*WS_ST + ow + 16*st];
                const float* wr1 = &Ws[(8*s + q4 + 4)*WS_ST + ow + 16*st];
                a2r[st][0] = __float_as_uint(wr0[g]);
                a2r[st][1] = __float_as_uint(wr0[g + 8]);
                a2r[st][2] = __float_as_uint(wr1[g]);
                a2r[st][3] = __float_as_uint(wr1[g + 8]);
            }
            const float* x0 = &Xs[(8*s + q4    )*XS_ST + nwp + g];
            const float* x1 = &Xs[(8*s + q4 + 4)*XS_ST + nwp + g];
            #pragma unroll
            for (int nc = 0; nc < 8; nc++) {
                uint32_t b0 = __float_as_uint(x0[8*nc]);
                uint32_t b1 = __float_as_uint(x1[8*nc]);
                mma_tf32(acc[0][nc], a2r[0], b0, b1, acc[0][nc]);
                mma_tf32(acc[1][nc], a2r[1], b0, b1, acc[1][nc]);
            }
        }
    }

    // ---- Epilogue ----
    #pragma unroll
    for (int st = 0; st < 2; st++) {
        const int row0 = o0 + ow + 16*st + g;
        const int row1 = row0 + 8;
        const float bi0 = bias[row0];
        const float bi1 = bias[row1];
        float inv0, add0, inv1, add1;
        if constexpr (MODE == 2) {
            inv0 = e0[row0] * rsqrtf(e3[row0] + 1e-5f);
            add0 = e1[row0] - e2[row0] * inv0;
            inv1 = e0[row1] * rsqrtf(e3[row1] + 1e-5f);
            add1 = e1[row1] - e2[row1] * inv1;
        }
        const size_t yb0 = ((size_t)b*Cout + row0) * N_;
        const size_t yb1 = ((size_t)b*Cout + row1) * N_;

        #pragma unroll
        for (int nc = 0; nc < 8; nc++) {
            const int n = n0 + nwp + 8*nc + 2*q4;
            float2 y0 = make_float2(acc[st][nc][0] + bi0, acc[st][nc][1] + bi0);
            float2 y1 = make_float2(acc[st][nc][2] + bi1, acc[st][nc][3] + bi1);
            if constexpr (MODE == 1) {
                float2 wv2 = *(const float2*)&e0[(size_t)b * N_ + n];
                y0.x *= wv2.x; y0.y *= wv2.y;
                y1.x *= wv2.x; y1.y *= wv2.y;
            }
            if constexpr (MODE == 2) {
                y0.x = fmaxf(fmaf(y0.x, inv0, add0), 0.f);
                y0.y = fmaxf(fmaf(y0.y, inv0, add0), 0.f);
                y1.x = fmaxf(fmaf(y1.x, inv1, add1), 0.f);
                y1.y = fmaxf(fmaf(y1.y, inv1, add1), 0.f);
            }
            if constexpr (MODE == 3) {
                float2 r0 = *(const float2*)&e0[yb0 + n];
                float2 r1 = *(const float2*)&e0[yb1 + n];
                y0.x += r0.x; y0.y += r0.y;
                y1.x += r1.x; y1.y += r1.y;
            }
            *(float2*)&Y[yb0 + n] = y0;
            *(float2*)&Y[yb1 + n] = y1;
        }
    }
}

// ---------------------------------------------------------------------------
// Attention via bf16 mma.m16n8k16, fp32 accumulation (FA style, deferred norm).
// CTA 128 thr / 4 warps; 64 n-rows (16/warp); m-tiles of 64.
// All operands packed as bf16x2 along the k-dim:
//   Qp[d/2][n]  (u32, stride 72)  A-frags for QK
//   Kp[d/2][m]  (u32, stride 72)  B-frags for QK
//   Vp[d][m/2]  (u32, stride 36)  B-frags for PV (pairs along m)
//   Pp[n][m/2]  (u32, stride 36)  per-warp A-frags for PV
// Fragment-load banks: 8*q4+g or 4*g+q4 — conflict-free by construction.
// ---------------------------------------------------------------------------
static constexpr int QK_ST = 72;   // u32
static constexpr int VP_ST = 36;   // u32
// smem map (u32): Qp 0..2304, Kp 2304..4608, Vp 4608..6912, Pp 6912..9216
static constexpr int SMEM_U32 = 9216;

__global__ void __launch_bounds__(128) attn_bf16(
    const float* __restrict__ Q, const float* __restrict__ K,
    const float* __restrict__ V, float* __restrict__ O)
{
    extern __shared__ uint32_t su[];
    uint32_t* Qp = su;
    uint32_t* Kp = su + 2304;
    uint32_t* Vp = su + 4608;
    uint32_t* Pp = su + 6912;

    const int bh = blockIdx.y;
    const int n0 = blockIdx.x * 64;
    const size_t base = (size_t)bh * 64 * 2048;
    const int t = threadIdx.x;
    const int lane = t & 31, w = t >> 5;
    const int g = lane >> 2, q4 = lane & 3;
    const int nw = w * 16;

    // ---- Pack Q: Qp[d'][n] = bf16x2{Q[2d'][n], Q[2d'+1][n]} ----
    #pragma unroll
    for (int it = 0; it < 4; it++) {
        int lin = it*128 + t;
        int dp = lin >> 4, nq = (lin & 15) << 2;
        const float* r0 = &Q[base + (size_t)(2*dp) * 2048 + n0 + nq];
        float4 a = *(const float4*)r0;
        float4 b = *(const float4*)(r0 + 2048);
        uint4 pk = make_uint4(pkbf(a.x,b.x), pkbf(a.y,b.y), pkbf(a.z,b.z), pkbf(a.w,b.w));
        *(uint4*)&Qp[dp*QK_ST + nq] = pk;
    }
    __syncthreads();

    // ---- Q A-fragments: 4 k16-chunks ----
    uint32_t qa[4][4];
    #pragma unroll
    for (int dc = 0; dc < 4; dc++) {
        qa[dc][0] = Qp[(8*dc + q4    )*QK_ST + nw + g];
        qa[dc][1] = Qp[(8*dc + q4    )*QK_ST + nw + g + 8];
        qa[dc][2] = Qp[(8*dc + q4 + 4)*QK_ST + nw + g];
        qa[dc][3] = Qp[(8*dc + q4 + 4)*QK_ST + nw + g + 8];
    }

    float o_[8][4];
    #pragma unroll
    for (int dc = 0; dc < 8; dc++)
        #pragma unroll
        for (int j = 0; j < 4; j++) o_[dc][j] = 0.f;
    float l0 = 0.f, l1 = 0.f;

    uint32_t* Pw = Pp + w * 16 * VP_ST;

    for (int m0 = 0; m0 < M_; m0 += 64) {
        __syncthreads();  // prior iter's Kp/Vp reads complete
        // ---- Pack K: Kp[d'][m] ----
        #pragma unroll
        for (int it = 0; it < 4; it++) {
            int lin = it*128 + t;
            int dp = lin >> 4, mq = (lin & 15) << 2;
            const float* r0 = &K[base + (size_t)(2*dp) * 2048 + m0 + mq];
            float4 a = *(const float4*)r0;
            float4 b = *(const float4*)(r0 + 2048);
            uint4 pk = make_uint4(pkbf(a.x,b.x), pkbf(a.y,b.y), pkbf(a.z,b.z), pkbf(a.w,b.w));
            *(uint4*)&Kp[dp*QK_ST + mq] = pk;
        }
        // ---- Pack V: Vp[d][mp] = bf16x2{V[d][2mp], V[d][2mp+1]} ----
        #pragma unroll
        for (int it = 0; it < 8; it++) {
            int lin = it*128 + t;
            int d = lin >> 4, mq = lin & 15;
            float4 v4 = *(const float4*)&V[base + (size_t)d * 2048 + m0 + 4*mq];
            uint2 pk = make_uint2(pkbf(v4.x, v4.y), pkbf(v4.z, v4.w));
            *(uint2*)&Vp[d*VP_ST + 2*mq] = pk;
        }
        __syncthreads();

        // ---- S = Q^T K ----
        float s[8][4];
        #pragma unroll
        for (int mc = 0; mc < 8; mc++)
            #pragma unroll
            for (int j = 0; j < 4; j++) s[mc][j] = 0.f;

        #pragma unroll
        for (int dc = 0; dc < 4; dc++) {
            const uint32_t* k0 = &Kp[(8*dc + q4    )*QK_ST + g];
            const uint32_t* k1 = &Kp[(8*dc + q4 + 4)*QK_ST + g];
            #pragma unroll
            for (int mc = 0; mc < 8; mc++)
                mma_bf16(s[mc], qa[dc], k0[8*mc], k1[8*mc], s[mc]);
        }

        // ---- P = exp(S/8); row sums; pack to warp-private strip ----
        #pragma unroll
        for (int mc = 0; mc < 8; mc++) {
            float e0 = __expf(s[mc][0] * 0.125f);
            float e1 = __expf(s[mc][1] * 0.125f);
            float e2 = __expf(s[mc][2] * 0.125f);
            float e3 = __expf(s[mc][3] * 0.125f);
            l0 += e0 + e1;
            l1 += e2 + e3;
            Pw[(g    )*VP_ST + 4*mc + q4] = pkbf(e0, e1);
            Pw[(g + 8)*VP_ST + 4*mc + q4] = pkbf(e2, e3);
        }
        __syncwarp();

        // ---- O += P V ----
        #pragma unroll
        for (int mkc = 0; mkc < 4; mkc++) {
            uint32_t pa[4];
            pa[0] = Pw[(g    )*VP_ST + 8*mkc + q4];
            pa[1] = Pw[(g + 8)*VP_ST + 8*mkc + q4];
            pa[2] = Pw[(g    )*VP_ST + 8*mkc + q4 + 4];
            pa[3] = Pw[(g + 8)*VP_ST + 8*mkc + q4 + 4];
            #pragma unroll
            for (int dc = 0; dc < 8; dc++) {
                const uint32_t* vr = &Vp[(8*dc + g)*VP_ST + 8*mkc];
                mma_bf16(o_[dc], pa, vr[q4], vr[q4 + 4], o_[dc]);
            }
        }
    }

    // ---- Normalize (reduce row sums over the 4 lanes of each group) ----
    l0 += __shfl_xor_sync(0xffffffffu, l0, 1);
    l0 += __shfl_xor_sync(0xffffffffu, l0, 2);
    l1 += __shfl_xor_sync(0xffffffffu, l1, 1);
    l1 += __shfl_xor_sync(0xffffffffu, l1, 2);
    const float inv0 = 1.0f / l0;
    const float inv1 = 1.0f / l1;

    // ---- Stage O as [d][n] (fp32, stride 72) and write coalesced ----
    __syncthreads();
    float* Os = (float*)su;
    #pragma unroll
    for (int dc = 0; dc < 8; dc++) {
        #pragma unroll
        for (int j = 0; j < 2; j++) {
            int d = 8*dc + 2*q4 + j;
            Os[d*QK_ST + nw + g    ] = o_[dc][j]     * inv0;
            Os[d*QK_ST + nw + g + 8] = o_[dc][2 + j] * inv1;
        }
    }
    __syncthreads();
    #pragma unroll
    for (int it = 0; it < 32; it++) {
        int lin = it*128 + t;
        int n = lin & 63, d = lin >> 6;
        O[base + (size_t)d * 2048 + n0 + n] = Os[d*QK_ST + n];
    }
}

// ---------------------------------------------------------------------------
extern "C" void kernel_launch(void* const* d_in, const int* in_sizes, int n_in,
                              void* d_out, int out_size)
{
    const float* desc1 = (const float*)d_in[0];
    const float* desc2 = (const float*)d_in[1];
    const float* wv    = (const float*)d_in[2];
    const float* Wq    = (const float*)d_in[3];
    const float* bq    = (const float*)d_in[4];
    const float* Wk    = (const float*)d_in[5];
    const float* bk    = (const float*)d_in[6];
    const float* Wv    = (const float*)d_in[7];
    const float* bv    = (const float*)d_in[8];
    const float* Wm    = (const float*)d_in[9];
    const float* bm    = (const float*)d_in[10];
    const float* Wc1   = (const float*)d_in[11];
    const float* bc1   = (const float*)d_in[12];
    const float* gamma = (const float*)d_in[13];
    const float* beta  = (const float*)d_in[14];
    const float* mean  = (const float*)d_in[15];
    const float* var   = (const float*)d_in[16];
    const float* Wc2   = (const float*)d_in[17];
    const float* bc2   = (const float*)d_in[18];
    float* out = (float*)d_out;

    float *q, *k, *v, *attn, *mo, *h;
    cudaGetSymbolAddress((void**)&q,    g_q);
    cudaGetSymbolAddress((void**)&k,    g_k);
    cudaGetSymbolAddress((void**)&v,    g_v);
    cudaGetSymbolAddress((void**)&attn, g_attn);
    cudaGetSymbolAddress((void**)&mo,   g_mo);
    cudaGetSymbolAddress((void**)&h,    g_h);

    const dim3 blk(128);
    const dim3 gp(N_/128, C_/64, B_);    // 16 x 4 x 8
    const dim3 gh(N_/128, 2*C_/64, B_);  // 16 x 8 x 8

    gemm_mma<0><<<gp, blk>>>(Wq, bq, desc1, nullptr, q, C_, C_, C_,
                             nullptr, nullptr, nullptr, nullptr);
    gemm_mma<0><<<gp, blk>>>(Wk, bk, desc2, nullptr, k, C_, C_, C_,
                             nullptr, nullptr, nullptr, nullptr);
    gemm_mma<1><<<gp, blk>>>(Wv, bv, desc2, nullptr, v, C_, C_, C_,
                             wv, nullptr, nullptr, nullptr);

    const int smem_bytes = SMEM_U32 * 4;  // 36864 B
    cudaFuncSetAttribute(attn_bf16, cudaFuncAttributeMaxDynamicSharedMemorySize, smem_bytes);
    attn_bf16<<<dim3(N_/64, B_*4), 128, smem_bytes>>>(q, k, v, attn);

    gemm_mma<0><<<gp, blk>>>(Wm, bm, attn, nullptr, mo, C_, C_, C_,
                             nullptr, nullptr, nullptr, nullptr);

    gemm_mma<2><<<gh, blk>>>(Wc1, bc1, desc1, mo, h, 2*C_, 2*C_, C_,
                             gamma, beta, mean, var);

    gemm_mma<3><<<gp, blk>>>(Wc2, bc2, h, nullptr, out, C_, 2*C_, 2*C_,
                             desc1, nullptr, nullptr, nullptr);
}

// round 12
// speedup vs baseline: 2.5378x; 1.7235x over previous
#include <cuda_runtime.h>
#include <cuda_bf16.h>
#include <math.h>
#include <stdint.h>

static constexpr int B_ = 8;
static constexpr int C_ = 256;
static constexpr int N_ = 2048;
static constexpr int M_ = 2048;

// Scratch (no cudaMalloc allowed)
__device__ uint32_t g_qp[B_*4*32*2048];   // packed bf16x2 pairs (d,d+8) per head
__device__ uint32_t g_kp[B_*4*32*2048];
__device__ uint32_t g_vp[B_*4*64*1024];   // packed bf16x2 pairs (m,m+1)
__device__ float    g_attn[B_*C_*N_];
__device__ float    g_mo[B_*C_*N_];
__device__ float    g_h[B_*2*C_*N_];

// ---------------------------------------------------------------------------
// helpers
// ---------------------------------------------------------------------------
__device__ __forceinline__ uint32_t s2u(const void* p) {
    return (uint32_t)__cvta_generic_to_shared(p);
}
#define CPA16(dst, src) \
    asm volatile("cp.async.cg.shared.global [%0], [%1], 16;" :: "r"(dst), "l"(src))
#define CPA_COMMIT() asm volatile("cp.async.commit_group;")
#define CPA_WAIT0()  asm volatile("cp.async.wait_group 0;")
#define CPA_WAIT1()  asm volatile("cp.async.wait_group 1;")

__device__ __forceinline__ void mma_tf32(
    float d[4], const uint32_t a[4], uint32_t b0, uint32_t b1, const float c[4])
{
    asm volatile(
        "mma.sync.aligned.m16n8k8.row.col.f32.tf32.tf32.f32 "
        "{%0,%1,%2,%3}, {%4,%5,%6,%7}, {%8,%9}, {%10,%11,%12,%13};"
        : "=f"(d[0]), "=f"(d[1]), "=f"(d[2]), "=f"(d[3])
        : "r"(a[0]), "r"(a[1]), "r"(a[2]), "r"(a[3]),
          "r"(b0), "r"(b1),
          "f"(c[0]), "f"(c[1]), "f"(c[2]), "f"(c[3]));
}

__device__ __forceinline__ void mma_bf16(
    float d[4], const uint32_t a[4], uint32_t b0, uint32_t b1, const float c[4])
{
    asm volatile(
        "mma.sync.aligned.m16n8k16.row.col.f32.bf16.bf16.f32 "
        "{%0,%1,%2,%3}, {%4,%5,%6,%7}, {%8,%9}, {%10,%11,%12,%13};"
        : "=f"(d[0]), "=f"(d[1]), "=f"(d[2]), "=f"(d[3])
        : "r"(a[0]), "r"(a[1]), "r"(a[2]), "r"(a[3]),
          "r"(b0), "r"(b1),
          "f"(c[0]), "f"(c[1]), "f"(c[2]), "f"(c[3]));
}

__device__ __forceinline__ uint32_t pkbf(float lo, float hi) {
    __nv_bfloat162 h = __floats2bfloat162_rn(lo, hi);
    return *(uint32_t*)&h;
}

// ---------------------------------------------------------------------------
// Tensor-core GEMM, cp.async 2-stage pipeline, tf32-by-truncation.
// Y[b][o][n] = epi( sum_i W[o][i] * X[b][i][n] + bias[o] ), concat via Ca.
// CTA 128 thr / 4 warps; tile 64 o x 128 n; K-chunk 32, double buffered.
// Ws[o][k] stride 36 (A-frag banks 4g+q4), Xs[k][n] stride 136 (8q4+g).
// MODE 0:+bias  2:BN+ReLU  3:+residual  4:pack QK-pairs  5:weight_v+pack V
// ---------------------------------------------------------------------------
static constexpr int WG_ST = 36;
static constexpr int XG_ST = 136;
static constexpr int GEMM_SMEM = (2*64*WG_ST + 2*32*XG_ST) * 4;  // 53248 B

template<int MODE>
__global__ void __launch_bounds__(128, 4) gemm_mma(
    const float* __restrict__ W, const float* __restrict__ bias,
    const float* __restrict__ Xa, const float* __restrict__ Xb,
    void* __restrict__ Yv, int Cout, int Cin, int Ca,
    const float* __restrict__ e0, const float* __restrict__ e1,
    const float* __restrict__ e2, const float* __restrict__ e3)
{
    extern __shared__ float sg[];
    float* Wb0 = sg;
    float* Wb1 = sg + 64*WG_ST;
    float* Xb0 = sg + 2*64*WG_ST;
    float* Xb1 = Xb0 + 32*XG_ST;

    const int b  = blockIdx.z;
    const int o0 = blockIdx.y * 64;
    const int n0 = blockIdx.x * 128;
    const int t  = threadIdx.x;
    const int lane = t & 31, w = t >> 5;
    const int g = lane >> 2, q4 = lane & 3;
    const int ow = (w & 1) * 32;
    const int nwp = (w >> 1) * 64;
    const int Cb = Cin - Ca;

    auto issue = [&](int i0, int bufi) {
        float* Wd = bufi ? Wb1 : Wb0;
        float* Xd = bufi ? Xb1 : Xb0;
        #pragma unroll
        for (int r = 0; r < 4; r++) {
            int ch = r*128 + t, row = ch >> 3, c4 = (ch & 7) << 2;
            CPA16(s2u(Wd + row*WG_ST + c4),
                  W + (size_t)(o0 + row) * Cin + i0 + c4);
        }
        #pragma unroll
        for (int r = 0; r < 8; r++) {
            int ch = r*128 + t, row = ch >> 5, c4 = (ch & 31) << 2;
            int ig = i0 + row;
            const float* src = (ig < Ca)
                ? Xa + ((size_t)b*Ca + ig) * N_ + n0 + c4
                : Xb + ((size_t)b*Cb + (ig - Ca)) * N_ + n0 + c4;
            CPA16(s2u(Xd + row*XG_ST + c4), src);
        }
        CPA_COMMIT();
    };

    float acc[2][8][4];
    #pragma unroll
    for (int st = 0; st < 2; st++)
        #pragma unroll
        for (int nc = 0; nc < 8; nc++)
            #pragma unroll
            for (int j = 0; j < 4; j++) acc[st][nc][j] = 0.f;

    const int nch = Cin >> 5;
    issue(0, 0);

    for (int i = 0; i < nch; i++) {
        CPA_WAIT0();
        __syncthreads();                 // chunk i visible; prev compute done
        if (i + 1 < nch) issue((i + 1) << 5, (i + 1) & 1);

        const float* Wc = (i & 1) ? Wb1 : Wb0;
        const float* Xc = (i & 1) ? Xb1 : Xb0;

        #pragma unroll
        for (int s = 0; s < 4; s++) {
            uint32_t a2r[2][4];
            #pragma unroll
            for (int st = 0; st < 2; st++) {
                const float* wr0 = &Wc[(ow + 16*st + g    )*WG_ST + 8*s + q4];
                const float* wr1 = &Wc[(ow + 16*st + g + 8)*WG_ST + 8*s + q4];
                a2r[st][0] = __float_as_uint(wr0[0]);
                a2r[st][1] = __float_as_uint(wr1[0]);
                a2r[st][2] = __float_as_uint(wr0[4]);
                a2r[st][3] = __float_as_uint(wr1[4]);
            }
            const float* x0 = &Xc[(8*s + q4    )*XG_ST + nwp + g];
            const float* x1 = &Xc[(8*s + q4 + 4)*XG_ST + nwp + g];
            #pragma unroll
            for (int nc = 0; nc < 8; nc++) {
                uint32_t b0 = __float_as_uint(x0[8*nc]);
                uint32_t b1 = __float_as_uint(x1[8*nc]);
                mma_tf32(acc[0][nc], a2r[0], b0, b1, acc[0][nc]);
                mma_tf32(acc[1][nc], a2r[1], b0, b1, acc[1][nc]);
            }
        }
    }

    // ---- Epilogue ----
    float* Y = (float*)Yv;
    uint32_t* Yp = (uint32_t*)Yv;

    #pragma unroll
    for (int st = 0; st < 2; st++) {
        const int row0 = o0 + ow + 16*st + g;
        const int row1 = row0 + 8;
        const float bi0 = bias[row0];
        const float bi1 = bias[row1];

        if constexpr (MODE == 4) {
            // pack pairs (row0, row0+8) within head -> qp/kp [bh][32][2048]
            const int d0 = row0 & 63, h = row0 >> 6;
            const size_t obase =
                (((size_t)b*4 + h)*32 + ((d0 >> 4)*8 + (d0 & 7))) * (size_t)N_;
            #pragma unroll
            for (int nc = 0; nc < 8; nc++) {
                const int n = n0 + nwp + 8*nc + 2*q4;
                Yp[obase + n    ] = pkbf(acc[st][nc][0] + bi0, acc[st][nc][2] + bi1);
                Yp[obase + n + 1] = pkbf(acc[st][nc][1] + bi0, acc[st][nc][3] + bi1);
            }
        } else if constexpr (MODE == 5) {
            // weight_v, pack adjacent n (m-pairs) -> vp [bh][64][1024]
            const int d0 = row0 & 63, h = row0 >> 6;
            const size_t b0v = (((size_t)b*4 + h)*64 + d0    ) * (size_t)(N_/2);
            const size_t b1v = (((size_t)b*4 + h)*64 + d0 + 8) * (size_t)(N_/2);
            #pragma unroll
            for (int nc = 0; nc < 8; nc++) {
                const int n = n0 + nwp + 8*nc + 2*q4;
                float2 wv2 = *(const float2*)&e0[(size_t)b * N_ + n];
                float y0x = (acc[st][nc][0] + bi0) * wv2.x;
                float y0y = (acc[st][nc][1] + bi0) * wv2.y;
                float y1x = (acc[st][nc][2] + bi1) * wv2.x;
                float y1y = (acc[st][nc][3] + bi1) * wv2.y;
                Yp[b0v + (n >> 1)] = pkbf(y0x, y0y);
                Yp[b1v + (n >> 1)] = pkbf(y1x, y1y);
            }
        } else {
            float inv0, add0, inv1, add1;
            if constexpr (MODE == 2) {
                inv0 = e0[row0] * rsqrtf(e3[row0] + 1e-5f);
                add0 = e1[row0] - e2[row0] * inv0;
                inv1 = e0[row1] * rsqrtf(e3[row1] + 1e-5f);
                add1 = e1[row1] - e2[row1] * inv1;
            }
            const size_t yb0 = ((size_t)b*Cout + row0) * N_;
            const size_t yb1 = ((size_t)b*Cout + row1) * N_;
            #pragma unroll
            for (int nc = 0; nc < 8; nc++) {
                const int n = n0 + nwp + 8*nc + 2*q4;
                float2 y0 = make_float2(acc[st][nc][0] + bi0, acc[st][nc][1] + bi0);
                float2 y1 = make_float2(acc[st][nc][2] + bi1, acc[st][nc][3] + bi1);
                if constexpr (MODE == 2) {
                    y0.x = fmaxf(fmaf(y0.x, inv0, add0), 0.f);
                    y0.y = fmaxf(fmaf(y0.y, inv0, add0), 0.f);
                    y1.x = fmaxf(fmaf(y1.x, inv1, add1), 0.f);
                    y1.y = fmaxf(fmaf(y1.y, inv1, add1), 0.f);
                }
                if constexpr (MODE == 3) {
                    float2 r0 = *(const float2*)&e0[yb0 + n];
                    float2 r1 = *(const float2*)&e0[yb1 + n];
                    y0.x += r0.x; y0.y += r0.y;
                    y1.x += r1.x; y1.y += r1.y;
                }
                *(float2*)&Y[yb0 + n] = y0;
                *(float2*)&Y[yb1 + n] = y1;
            }
        }
    }
}

// ---------------------------------------------------------------------------
// Attention, bf16 mma, pre-packed inputs, cp.async double-buffered K/V.
// QP/KP: [bh][32 dp][2048] u32 (bf16x2 pairs along d, pairing (d,d+8))
// VP:    [bh][64 d][1024]  u32 (bf16x2 pairs along m)
// smem (u32): Qs 32x72 | Kb0,Kb1 32x72 | Vb0,Vb1 64x36 | Pp 4x(16x36)
// ---------------------------------------------------------------------------
static constexpr int QK_ST = 72;   // u32
static constexpr int VP_ST = 36;   // u32
static constexpr int ATT_SMEM = (32*QK_ST*3 + 64*VP_ST*2 + 64*VP_ST) * 4; // 55296

__global__ void __launch_bounds__(128) attn_bf16(
    const uint32_t* __restrict__ QP, const uint32_t* __restrict__ KP,
    const uint32_t* __restrict__ VP, float* __restrict__ O)
{
    extern __shared__ uint32_t su[];
    uint32_t* Qs  = su;                       // 2304
    uint32_t* Kb0 = su + 2304;
    uint32_t* Kb1 = su + 4608;
    uint32_t* Vb0 = su + 6912;
    uint32_t* Vb1 = su + 9216;
    uint32_t* Pp  = su + 11520;

    const int bh = blockIdx.y;
    const int n0 = blockIdx.x * 64;
    const size_t qkb = (size_t)bh * 32 * 2048;
    const size_t vb  = (size_t)bh * 64 * 1024;
    const int t = threadIdx.x;
    const int lane = t & 31, w = t >> 5;
    const int g = lane >> 2, q4 = lane & 3;
    const int nw = w * 16;

    auto issue_kv = [&](int m0, int bufi) {
        uint32_t* Kd = bufi ? Kb1 : Kb0;
        uint32_t* Vd = bufi ? Vb1 : Vb0;
        #pragma unroll
        for (int r = 0; r < 4; r++) {
            int ch = r*128 + t, row = ch >> 4, c4 = (ch & 15) << 2;
            CPA16(s2u(Kd + row*QK_ST + c4), KP + qkb + (size_t)row*2048 + m0 + c4);
        }
        #pragma unroll
        for (int r = 0; r < 4; r++) {
            int ch = r*128 + t, row = ch >> 3, c4 = (ch & 7) << 2;
            CPA16(s2u(Vd + row*VP_ST + c4), VP + vb + (size_t)row*1024 + (m0 >> 1) + c4);
        }
        CPA_COMMIT();
    };

    // Prologue: Q copies (group 0), then KV tile 0 (group 1)
    #pragma unroll
    for (int r = 0; r < 4; r++) {
        int ch = r*128 + t, row = ch >> 4, c4 = (ch & 15) << 2;
        CPA16(s2u(Qs + row*QK_ST + c4), QP + qkb + (size_t)row*2048 + n0 + c4);
    }
    CPA_COMMIT();
    issue_kv(0, 0);
    CPA_WAIT1();          // Q done (KV0 may still be in flight)
    __syncthreads();

    // Q A-fragments
    uint32_t qa[4][4];
    #pragma unroll
    for (int dc = 0; dc < 4; dc++) {
        qa[dc][0] = Qs[(8*dc + q4    )*QK_ST + nw + g];
        qa[dc][1] = Qs[(8*dc + q4    )*QK_ST + nw + g + 8];
        qa[dc][2] = Qs[(8*dc + q4 + 4)*QK_ST + nw + g];
        qa[dc][3] = Qs[(8*dc + q4 + 4)*QK_ST + nw + g + 8];
    }

    float o_[8][4];
    #pragma unroll
    for (int dc = 0; dc < 8; dc++)
        #pragma unroll
        for (int j = 0; j < 4; j++) o_[dc][j] = 0.f;
    float l0 = 0.f, l1 = 0.f;

    uint32_t* Pw = Pp + w * 16 * VP_ST;

    for (int i = 0; i < M_/64; i++) {
        CPA_WAIT0();
        __syncthreads();                       // KV tile i ready; prev reads done
        if (i + 1 < M_/64) issue_kv((i + 1) * 64, (i + 1) & 1);

        const uint32_t* Kc = (i & 1) ? Kb1 : Kb0;
        const uint32_t* Vc = (i & 1) ? Vb1 : Vb0;

        // ---- S = Q^T K ----
        float s[8][4];
        #pragma unroll
        for (int mc = 0; mc < 8; mc++)
            #pragma unroll
            for (int j = 0; j < 4; j++) s[mc][j] = 0.f;

        #pragma unroll
        for (int dc = 0; dc < 4; dc++) {
            const uint32_t* k0 = &Kc[(8*dc + q4    )*QK_ST + g];
            const uint32_t* k1 = &Kc[(8*dc + q4 + 4)*QK_ST + g];
            #pragma unroll
            for (int mc = 0; mc < 8; mc++)
                mma_bf16(s[mc], qa[dc], k0[8*mc], k1[8*mc], s[mc]);
        }

        // ---- P = exp(S/8); row sums; warp-private strip ----
        #pragma unroll
        for (int mc = 0; mc < 8; mc++) {
            float e0 = __expf(s[mc][0] * 0.125f);
            float e1 = __expf(s[mc][1] * 0.125f);
            float e2 = __expf(s[mc][2] * 0.125f);
            float e3 = __expf(s[mc][3] * 0.125f);
            l0 += e0 + e1;
            l1 += e2 + e3;
            Pw[(g    )*VP_ST + 4*mc + q4] = pkbf(e0, e1);
            Pw[(g + 8)*VP_ST + 4*mc + q4] = pkbf(e2, e3);
        }
        __syncwarp();

        // ---- O += P V ----
        #pragma unroll
        for (int mkc = 0; mkc < 4; mkc++) {
            uint32_t pa[4];
            pa[0] = Pw[(g    )*VP_ST + 8*mkc + q4];
            pa[1] = Pw[(g + 8)*VP_ST + 8*mkc + q4];
            pa[2] = Pw[(g    )*VP_ST + 8*mkc + q4 + 4];
            pa[3] = Pw[(g + 8)*VP_ST + 8*mkc + q4 + 4];
            #pragma unroll
            for (int dc = 0; dc < 8; dc++) {
                const uint32_t* vr = &Vc[(8*dc + g)*VP_ST + 8*mkc];
                mma_bf16(o_[dc], pa, vr[q4], vr[q4 + 4], o_[dc]);
            }
        }
    }

    // ---- Normalize ----
    l0 += __shfl_xor_sync(0xffffffffu, l0, 1);
    l0 += __shfl_xor_sync(0xffffffffu, l0, 2);
    l1 += __shfl_xor_sync(0xffffffffu, l1, 1);
    l1 += __shfl_xor_sync(0xffffffffu, l1, 2);
    const float inv0 = 1.0f / l0;
    const float inv1 = 1.0f / l1;

    // ---- Stage O [d][n] fp32 (region su[0..4608) = Qs+Kb0, both dead) ----
    __syncthreads();
    float* Os = (float*)su;
    #pragma unroll
    for (int dc = 0; dc < 8; dc++) {
        #pragma unroll
        for (int j = 0; j < 2; j++) {
            int d = 8*dc + 2*q4 + j;
            Os[d*QK_ST + nw + g    ] = o_[dc][j]     * inv0;
            Os[d*QK_ST + nw + g + 8] = o_[dc][2 + j] * inv1;
        }
    }
    __syncthreads();
    const size_t obase = (size_t)bh * 64 * 2048;
    #pragma unroll
    for (int it = 0; it < 32; it++) {
        int lin = it*128 + t;
        int n = lin & 63, d = lin >> 6;
        O[obase + (size_t)d * 2048 + n0 + n] = Os[d*QK_ST + n];
    }
}

// ---------------------------------------------------------------------------
extern "C" void kernel_launch(void* const* d_in, const int* in_sizes, int n_in,
                              void* d_out, int out_size)
{
    const float* desc1 = (const float*)d_in[0];
    const float* desc2 = (const float*)d_in[1];
    const float* wv    = (const float*)d_in[2];
    const float* Wq    = (const float*)d_in[3];
    const float* bq    = (const float*)d_in[4];
    const float* Wk    = (const float*)d_in[5];
    const float* bk    = (const float*)d_in[6];
    const float* Wv    = (const float*)d_in[7];
    const float* bv    = (const float*)d_in[8];
    const float* Wm    = (const float*)d_in[9];
    const float* bm    = (const float*)d_in[10];
    const float* Wc1   = (const float*)d_in[11];
    const float* bc1   = (const float*)d_in[12];
    const float* gamma = (const float*)d_in[13];
    const float* beta  = (const float*)d_in[14];
    const float* mean  = (const float*)d_in[15];
    const float* var   = (const float*)d_in[16];
    const float* Wc2   = (const float*)d_in[17];
    const float* bc2   = (const float*)d_in[18];
    float* out = (float*)d_out;

    uint32_t *qp, *kp, *vp;
    float *attn, *mo, *h;
    cudaGetSymbolAddress((void**)&qp,   g_qp);
    cudaGetSymbolAddress((void**)&kp,   g_kp);
    cudaGetSymbolAddress((void**)&vp,   g_vp);
    cudaGetSymbolAddress((void**)&attn, g_attn);
    cudaGetSymbolAddress((void**)&mo,   g_mo);
    cudaGetSymbolAddress((void**)&h,    g_h);

    cudaFuncSetAttribute(gemm_mma<0>, cudaFuncAttributeMaxDynamicSharedMemorySize, GEMM_SMEM);
    cudaFuncSetAttribute(gemm_mma<2>, cudaFuncAttributeMaxDynamicSharedMemorySize, GEMM_SMEM);
    cudaFuncSetAttribute(gemm_mma<3>, cudaFuncAttributeMaxDynamicSharedMemorySize, GEMM_SMEM);
    cudaFuncSetAttribute(gemm_mma<4>, cudaFuncAttributeMaxDynamicSharedMemorySize, GEMM_SMEM);
    cudaFuncSetAttribute(gemm_mma<5>, cudaFuncAttributeMaxDynamicSharedMemorySize, GEMM_SMEM);
    cudaFuncSetAttribute(attn_bf16,  cudaFuncAttributeMaxDynamicSharedMemorySize, ATT_SMEM);

    const dim3 blk(128);
    const dim3 gp(N_/128, C_/64, B_);    // 16 x 4 x 8
    const dim3 gh(N_/128, 2*C_/64, B_);  // 16 x 8 x 8

    // Projections -> packed bf16 operands
    gemm_mma<4><<<gp, blk, GEMM_SMEM>>>(Wq, bq, desc1, nullptr, qp, C_, C_, C_,
                                        nullptr, nullptr, nullptr, nullptr);
    gemm_mma<4><<<gp, blk, GEMM_SMEM>>>(Wk, bk, desc2, nullptr, kp, C_, C_, C_,
                                        nullptr, nullptr, nullptr, nullptr);
    gemm_mma<5><<<gp, blk, GEMM_SMEM>>>(Wv, bv, desc2, nullptr, vp, C_, C_, C_,
                                        wv, nullptr, nullptr, nullptr);

    attn_bf16<<<dim3(N_/64, B_*4), 128, ATT_SMEM>>>(qp, kp, vp, attn);

    gemm_mma<0><<<gp, blk, GEMM_SMEM>>>(Wm, bm, attn, nullptr, mo, C_, C_, C_,
                                        nullptr, nullptr, nullptr, nullptr);

    gemm_mma<2><<<gh, blk, GEMM_SMEM>>>(Wc1, bc1, desc1, mo, h, 2*C_, 2*C_, C_,
                                        gamma, beta, mean, var);

    gemm_mma<3><<<gp, blk, GEMM_SMEM>>>(Wc2, bc2, h, nullptr, out, C_, 2*C_, 2*C_,
                                        desc1, nullptr, nullptr, nullptr);
}

// round 13
// speedup vs baseline: 2.5812x; 1.0171x over previous
#include <cuda_runtime.h>
#include <cuda_bf16.h>
#include <math.h>
#include <stdint.h>

static constexpr int B_ = 8;
static constexpr int C_ = 256;
static constexpr int N_ = 2048;
static constexpr int M_ = 2048;

// Scratch (no cudaMalloc allowed)
__device__ uint32_t g_qp[B_*4*32*2048];   // packed bf16x2 pairs (d,d+8) per head
__device__ uint32_t g_kp[B_*4*32*2048];
__device__ uint32_t g_vp[B_*4*64*1024];   // packed bf16x2 pairs (m,m+1)
__device__ float    g_attn[B_*C_*N_];
__device__ float    g_mo[B_*C_*N_];
__device__ float    g_h[B_*2*C_*N_];

// ---------------------------------------------------------------------------
// helpers
// ---------------------------------------------------------------------------
__device__ __forceinline__ uint32_t s2u(const void* p) {
    return (uint32_t)__cvta_generic_to_shared(p);
}
#define CPA16(dst, src) \
    asm volatile("cp.async.cg.shared.global [%0], [%1], 16;" :: "r"(dst), "l"(src))
#define CPA_COMMIT() asm volatile("cp.async.commit_group;")
#define CPA_WAIT0()  asm volatile("cp.async.wait_group 0;")
#define CPA_WAIT1()  asm volatile("cp.async.wait_group 1;")

__device__ __forceinline__ void mma_tf32(
    float d[4], const uint32_t a[4], uint32_t b0, uint32_t b1, const float c[4])
{
    asm volatile(
        "mma.sync.aligned.m16n8k8.row.col.f32.tf32.tf32.f32 "
        "{%0,%1,%2,%3}, {%4,%5,%6,%7}, {%8,%9}, {%10,%11,%12,%13};"
        : "=f"(d[0]), "=f"(d[1]), "=f"(d[2]), "=f"(d[3])
        : "r"(a[0]), "r"(a[1]), "r"(a[2]), "r"(a[3]),
          "r"(b0), "r"(b1),
          "f"(c[0]), "f"(c[1]), "f"(c[2]), "f"(c[3]));
}

__device__ __forceinline__ void mma_bf16(
    float d[4], const uint32_t a[4], uint32_t b0, uint32_t b1, const float c[4])
{
    asm volatile(
        "mma.sync.aligned.m16n8k16.row.col.f32.bf16.bf16.f32 "
        "{%0,%1,%2,%3}, {%4,%5,%6,%7}, {%8,%9}, {%10,%11,%12,%13};"
        : "=f"(d[0]), "=f"(d[1]), "=f"(d[2]), "=f"(d[3])
        : "r"(a[0]), "r"(a[1]), "r"(a[2]), "r"(a[3]),
          "r"(b0), "r"(b1),
          "f"(c[0]), "f"(c[1]), "f"(c[2]), "f"(c[3]));
}

__device__ __forceinline__ uint32_t pkbf(float lo, float hi) {
    __nv_bfloat162 h = __floats2bfloat162_rn(lo, hi);
    return *(uint32_t*)&h;
}

// ---------------------------------------------------------------------------
// Shared GEMM tile geometry (64 o x 128 n, K-chunk 32, 2-stage cp.async)
// ---------------------------------------------------------------------------
static constexpr int WG_ST = 36;
static constexpr int XG_ST = 136;
static constexpr int GEMM_SMEM = (2*64*WG_ST + 2*32*XG_ST) * 4;  // 53248 B

// ---------------------------------------------------------------------------
// Fused Q/K/V projection: one launch, blockIdx.z = p*8 + b  (p: 0=Q 1=K 2=V).
// Outputs packed bf16x2 operands for the attention kernel.
// ---------------------------------------------------------------------------
__global__ void __launch_bounds__(128, 4) gemm_qkv(
    const float* __restrict__ Wq, const float* __restrict__ bq,
    const float* __restrict__ Wk, const float* __restrict__ bk,
    const float* __restrict__ Wv, const float* __restrict__ bv,
    const float* __restrict__ desc1, const float* __restrict__ desc2,
    const float* __restrict__ wv,
    uint32_t* __restrict__ qp, uint32_t* __restrict__ kp, uint32_t* __restrict__ vp)
{
    extern __shared__ float sg[];
    float* Wb0 = sg;
    float* Wb1 = sg + 64*WG_ST;
    float* Xb0 = sg + 2*64*WG_ST;
    float* Xb1 = Xb0 + 32*XG_ST;

    const int p  = blockIdx.z >> 3;
    const int b  = blockIdx.z & 7;
    const float* W    = (p == 0) ? Wq : (p == 1) ? Wk : Wv;
    const float* bias = (p == 0) ? bq : (p == 1) ? bk : bv;
    const float* X    = (p == 0) ? desc1 : desc2;
    uint32_t* Yp      = (p == 0) ? qp : (p == 1) ? kp : vp;

    const int o0 = blockIdx.y * 64;
    const int n0 = blockIdx.x * 128;
    const int t  = threadIdx.x;
    const int lane = t & 31, w = t >> 5;
    const int g = lane >> 2, q4 = lane & 3;
    const int ow = (w & 1) * 32;
    const int nwp = (w >> 1) * 64;

    auto issue = [&](int i0, int bufi) {
        float* Wd = bufi ? Wb1 : Wb0;
        float* Xd = bufi ? Xb1 : Xb0;
        #pragma unroll
        for (int r = 0; r < 4; r++) {
            int ch = r*128 + t, row = ch >> 3, c4 = (ch & 7) << 2;
            CPA16(s2u(Wd + row*WG_ST + c4), W + (size_t)(o0 + row) * C_ + i0 + c4);
        }
        #pragma unroll
        for (int r = 0; r < 8; r++) {
            int ch = r*128 + t, row = ch >> 5, c4 = (ch & 31) << 2;
            CPA16(s2u(Xd + row*XG_ST + c4),
                  X + ((size_t)b*C_ + i0 + row) * N_ + n0 + c4);
        }
        CPA_COMMIT();
    };

    float acc[2][8][4];
    #pragma unroll
    for (int st = 0; st < 2; st++)
        #pragma unroll
        for (int nc = 0; nc < 8; nc++)
            #pragma unroll
            for (int j = 0; j < 4; j++) acc[st][nc][j] = 0.f;

    issue(0, 0);
    for (int i = 0; i < C_/32; i++) {
        CPA_WAIT0();
        __syncthreads();
        if (i + 1 < C_/32) issue((i + 1) << 5, (i + 1) & 1);

        const float* Wc = (i & 1) ? Wb1 : Wb0;
        const float* Xc = (i & 1) ? Xb1 : Xb0;

        #pragma unroll
        for (int s = 0; s < 4; s++) {
            uint32_t a2r[2][4];
            #pragma unroll
            for (int st = 0; st < 2; st++) {
                const float* wr0 = &Wc[(ow + 16*st + g    )*WG_ST + 8*s + q4];
                const float* wr1 = &Wc[(ow + 16*st + g + 8)*WG_ST + 8*s + q4];
                a2r[st][0] = __float_as_uint(wr0[0]);
                a2r[st][1] = __float_as_uint(wr1[0]);
                a2r[st][2] = __float_as_uint(wr0[4]);
                a2r[st][3] = __float_as_uint(wr1[4]);
            }
            const float* x0 = &Xc[(8*s + q4    )*XG_ST + nwp + g];
            const float* x1 = &Xc[(8*s + q4 + 4)*XG_ST + nwp + g];
            #pragma unroll
            for (int nc = 0; nc < 8; nc++) {
                uint32_t b0 = __float_as_uint(x0[8*nc]);
                uint32_t b1 = __float_as_uint(x1[8*nc]);
                mma_tf32(acc[0][nc], a2r[0], b0, b1, acc[0][nc]);
                mma_tf32(acc[1][nc], a2r[1], b0, b1, acc[1][nc]);
            }
        }
    }

    // ---- Epilogue: pack ----
    #pragma unroll
    for (int st = 0; st < 2; st++) {
        const int row0 = o0 + ow + 16*st + g;
        const int row1 = row0 + 8;
        const float bi0 = bias[row0];
        const float bi1 = bias[row1];
        const int d0 = row0 & 63, h = row0 >> 6;

        if (p < 2) {
            // pack pairs (row0, row0+8) -> [bh][32][2048]
            const size_t obase =
                (((size_t)b*4 + h)*32 + ((d0 >> 4)*8 + (d0 & 7))) * (size_t)N_;
            #pragma unroll
            for (int nc = 0; nc < 8; nc++) {
                const int n = n0 + nwp + 8*nc + 2*q4;
                Yp[obase + n    ] = pkbf(acc[st][nc][0] + bi0, acc[st][nc][2] + bi1);
                Yp[obase + n + 1] = pkbf(acc[st][nc][1] + bi0, acc[st][nc][3] + bi1);
            }
        } else {
            // weight_v, pack adjacent n -> [bh][64][1024]
            const size_t b0v = (((size_t)b*4 + h)*64 + d0    ) * (size_t)(N_/2);
            const size_t b1v = (((size_t)b*4 + h)*64 + d0 + 8) * (size_t)(N_/2);
            #pragma unroll
            for (int nc = 0; nc < 8; nc++) {
                const int n = n0 + nwp + 8*nc + 2*q4;
                float2 wv2 = *(const float2*)&wv[(size_t)b * N_ + n];
                Yp[b0v + (n >> 1)] = pkbf((acc[st][nc][0] + bi0) * wv2.x,
                                          (acc[st][nc][1] + bi0) * wv2.y);
                Yp[b1v + (n >> 1)] = pkbf((acc[st][nc][2] + bi1) * wv2.x,
                                          (acc[st][nc][3] + bi1) * wv2.y);
            }
        }
    }
}

// ---------------------------------------------------------------------------
// General tensor-core GEMM (tf32) with fused epilogue — Wm / Wc1 / Wc2.
// MODE 0:+bias  2:BN+ReLU  3:+residual ; concat via Ca.
// ---------------------------------------------------------------------------
template<int MODE>
__global__ void __launch_bounds__(128, 4) gemm_mma(
    const float* __restrict__ W, const float* __restrict__ bias,
    const float* __restrict__ Xa, const float* __restrict__ Xb,
    float* __restrict__ Y, int Cout, int Cin, int Ca,
    const float* __restrict__ e0, const float* __restrict__ e1,
    const float* __restrict__ e2, const float* __restrict__ e3)
{
    extern __shared__ float sg[];
    float* Wb0 = sg;
    float* Wb1 = sg + 64*WG_ST;
    float* Xb0 = sg + 2*64*WG_ST;
    float* Xb1 = Xb0 + 32*XG_ST;

    const int b  = blockIdx.z;
    const int o0 = blockIdx.y * 64;
    const int n0 = blockIdx.x * 128;
    const int t  = threadIdx.x;
    const int lane = t & 31, w = t >> 5;
    const int g = lane >> 2, q4 = lane & 3;
    const int ow = (w & 1) * 32;
    const int nwp = (w >> 1) * 64;
    const int Cb = Cin - Ca;

    auto issue = [&](int i0, int bufi) {
        float* Wd = bufi ? Wb1 : Wb0;
        float* Xd = bufi ? Xb1 : Xb0;
        #pragma unroll
        for (int r = 0; r < 4; r++) {
            int ch = r*128 + t, row = ch >> 3, c4 = (ch & 7) << 2;
            CPA16(s2u(Wd + row*WG_ST + c4), W + (size_t)(o0 + row) * Cin + i0 + c4);
        }
        #pragma unroll
        for (int r = 0; r < 8; r++) {
            int ch = r*128 + t, row = ch >> 5, c4 = (ch & 31) << 2;
            int ig = i0 + row;
            const float* src = (ig < Ca)
                ? Xa + ((size_t)b*Ca + ig) * N_ + n0 + c4
                : Xb + ((size_t)b*Cb + (ig - Ca)) * N_ + n0 + c4;
            CPA16(s2u(Xd + row*XG_ST + c4), src);
        }
        CPA_COMMIT();
    };

    float acc[2][8][4];
    #pragma unroll
    for (int st = 0; st < 2; st++)
        #pragma unroll
        for (int nc = 0; nc < 8; nc++)
            #pragma unroll
            for (int j = 0; j < 4; j++) acc[st][nc][j] = 0.f;

    const int nch = Cin >> 5;
    issue(0, 0);
    for (int i = 0; i < nch; i++) {
        CPA_WAIT0();
        __syncthreads();
        if (i + 1 < nch) issue((i + 1) << 5, (i + 1) & 1);

        const float* Wc = (i & 1) ? Wb1 : Wb0;
        const float* Xc = (i & 1) ? Xb1 : Xb0;

        #pragma unroll
        for (int s = 0; s < 4; s++) {
            uint32_t a2r[2][4];
            #pragma unroll
            for (int st = 0; st < 2; st++) {
                const float* wr0 = &Wc[(ow + 16*st + g    )*WG_ST + 8*s + q4];
                const float* wr1 = &Wc[(ow + 16*st + g + 8)*WG_ST + 8*s + q4];
                a2r[st][0] = __float_as_uint(wr0[0]);
                a2r[st][1] = __float_as_uint(wr1[0]);
                a2r[st][2] = __float_as_uint(wr0[4]);
                a2r[st][3] = __float_as_uint(wr1[4]);
            }
            const float* x0 = &Xc[(8*s + q4    )*XG_ST + nwp + g];
            const float* x1 = &Xc[(8*s + q4 + 4)*XG_ST + nwp + g];
            #pragma unroll
            for (int nc = 0; nc < 8; nc++) {
                uint32_t b0 = __float_as_uint(x0[8*nc]);
                uint32_t b1 = __float_as_uint(x1[8*nc]);
                mma_tf32(acc[0][nc], a2r[0], b0, b1, acc[0][nc]);
                mma_tf32(acc[1][nc], a2r[1], b0, b1, acc[1][nc]);
            }
        }
    }

    #pragma unroll
    for (int st = 0; st < 2; st++) {
        const int row0 = o0 + ow + 16*st + g;
        const int row1 = row0 + 8;
        const float bi0 = bias[row0];
        const float bi1 = bias[row1];
        float inv0, add0, inv1, add1;
        if constexpr (MODE == 2) {
            inv0 = e0[row0] * rsqrtf(e3[row0] + 1e-5f);
            add0 = e1[row0] - e2[row0] * inv0;
            inv1 = e0[row1] * rsqrtf(e3[row1] + 1e-5f);
            add1 = e1[row1] - e2[row1] * inv1;
        }
        const size_t yb0 = ((size_t)b*Cout + row0) * N_;
        const size_t yb1 = ((size_t)b*Cout + row1) * N_;
        #pragma unroll
        for (int nc = 0; nc < 8; nc++) {
            const int n = n0 + nwp + 8*nc + 2*q4;
            float2 y0 = make_float2(acc[st][nc][0] + bi0, acc[st][nc][1] + bi0);
            float2 y1 = make_float2(acc[st][nc][2] + bi1, acc[st][nc][3] + bi1);
            if constexpr (MODE == 2) {
                y0.x = fmaxf(fmaf(y0.x, inv0, add0), 0.f);
                y0.y = fmaxf(fmaf(y0.y, inv0, add0), 0.f);
                y1.x = fmaxf(fmaf(y1.x, inv1, add1), 0.f);
                y1.y = fmaxf(fmaf(y1.y, inv1, add1), 0.f);
            }
            if constexpr (MODE == 3) {
                float2 r0 = *(const float2*)&e0[yb0 + n];
                float2 r1 = *(const float2*)&e0[yb1 + n];
                y0.x += r0.x; y0.y += r0.y;
                y1.x += r1.x; y1.y += r1.y;
            }
            *(float2*)&Y[yb0 + n] = y0;
            *(float2*)&Y[yb1 + n] = y1;
        }
    }
}

// ---------------------------------------------------------------------------
// Attention, bf16 mma, register-resident P (QK C-frag == PV A-frag layout).
// QP/KP: [bh][32 dp][2048] u32 ; VP: [bh][64 d][1024] u32.
// smem (u32): Qs 32x72 | Kb0,Kb1 32x72 | Vb0,Vb1 64x36   (no P strip)
// ---------------------------------------------------------------------------
static constexpr int QK_ST = 72;   // u32
static constexpr int VP_ST = 36;   // u32
static constexpr int ATT_SMEM = (32*QK_ST*3 + 64*VP_ST*2) * 4;  // 46080 B

__global__ void __launch_bounds__(128) attn_bf16(
    const uint32_t* __restrict__ QP, const uint32_t* __restrict__ KP,
    const uint32_t* __restrict__ VP, float* __restrict__ O)
{
    extern __shared__ uint32_t su[];
    uint32_t* Qs  = su;                       // 2304
    uint32_t* Kb0 = su + 2304;
    uint32_t* Kb1 = su + 4608;
    uint32_t* Vb0 = su + 6912;
    uint32_t* Vb1 = su + 9216;

    const int bh = blockIdx.y;
    const int n0 = blockIdx.x * 64;
    const size_t qkb = (size_t)bh * 32 * 2048;
    const size_t vb  = (size_t)bh * 64 * 1024;
    const int t = threadIdx.x;
    const int lane = t & 31, w = t >> 5;
    const int g = lane >> 2, q4 = lane & 3;
    const int nw = w * 16;

    auto issue_kv = [&](int m0, int bufi) {
        uint32_t* Kd = bufi ? Kb1 : Kb0;
        uint32_t* Vd = bufi ? Vb1 : Vb0;
        #pragma unroll
        for (int r = 0; r < 4; r++) {
            int ch = r*128 + t, row = ch >> 4, c4 = (ch & 15) << 2;
            CPA16(s2u(Kd + row*QK_ST + c4), KP + qkb + (size_t)row*2048 + m0 + c4);
        }
        #pragma unroll
        for (int r = 0; r < 4; r++) {
            int ch = r*128 + t, row = ch >> 3, c4 = (ch & 7) << 2;
            CPA16(s2u(Vd + row*VP_ST + c4), VP + vb + (size_t)row*1024 + (m0 >> 1) + c4);
        }
        CPA_COMMIT();
    };

    // Prologue: Q (group 0), KV tile 0 (group 1)
    #pragma unroll
    for (int r = 0; r < 4; r++) {
        int ch = r*128 + t, row = ch >> 4, c4 = (ch & 15) << 2;
        CPA16(s2u(Qs + row*QK_ST + c4), QP + qkb + (size_t)row*2048 + n0 + c4);
    }
    CPA_COMMIT();
    issue_kv(0, 0);
    CPA_WAIT1();
    __syncthreads();

    uint32_t qa[4][4];
    #pragma unroll
    for (int dc = 0; dc < 4; dc++) {
        qa[dc][0] = Qs[(8*dc + q4    )*QK_ST + nw + g];
        qa[dc][1] = Qs[(8*dc + q4    )*QK_ST + nw + g + 8];
        qa[dc][2] = Qs[(8*dc + q4 + 4)*QK_ST + nw + g];
        qa[dc][3] = Qs[(8*dc + q4 + 4)*QK_ST + nw + g + 8];
    }

    float o_[8][4];
    #pragma unroll
    for (int dc = 0; dc < 8; dc++)
        #pragma unroll
        for (int j = 0; j < 4; j++) o_[dc][j] = 0.f;
    float l0 = 0.f, l1 = 0.f;

    for (int i = 0; i < M_/64; i++) {
        CPA_WAIT0();
        __syncthreads();
        if (i + 1 < M_/64) issue_kv((i + 1) * 64, (i + 1) & 1);

        const uint32_t* Kc = (i & 1) ? Kb1 : Kb0;
        const uint32_t* Vc = (i & 1) ? Vb1 : Vb0;

        // ---- S = Q^T K ----
        float s[8][4];
        #pragma unroll
        for (int mc = 0; mc < 8; mc++)
            #pragma unroll
            for (int j = 0; j < 4; j++) s[mc][j] = 0.f;

        #pragma unroll
        for (int dc = 0; dc < 4; dc++) {
            const uint32_t* k0 = &Kc[(8*dc + q4    )*QK_ST + g];
            const uint32_t* k1 = &Kc[(8*dc + q4 + 4)*QK_ST + g];
            #pragma unroll
            for (int mc = 0; mc < 8; mc++)
                mma_bf16(s[mc], qa[dc], k0[8*mc], k1[8*mc], s[mc]);
        }

        // ---- P = exp(S/8) in-place; row sums ----
        #pragma unroll
        for (int mc = 0; mc < 8; mc++) {
            s[mc][0] = __expf(s[mc][0] * 0.125f);
            s[mc][1] = __expf(s[mc][1] * 0.125f);
            s[mc][2] = __expf(s[mc][2] * 0.125f);
            s[mc][3] = __expf(s[mc][3] * 0.125f);
            l0 += s[mc][0] + s[mc][1];
            l1 += s[mc][2] + s[mc][3];
        }

        // ---- O += P V : P A-fragments built directly from registers ----
        #pragma unroll
        for (int mkc = 0; mkc < 4; mkc++) {
            uint32_t pa[4];
            pa[0] = pkbf(s[2*mkc  ][0], s[2*mkc  ][1]);
            pa[1] = pkbf(s[2*mkc  ][2], s[2*mkc  ][3]);
            pa[2] = pkbf(s[2*mkc+1][0], s[2*mkc+1][1]);
            pa[3] = pkbf(s[2*mkc+1][2], s[2*mkc+1][3]);
            #pragma unroll
            for (int dc = 0; dc < 8; dc++) {
                const uint32_t* vr = &Vc[(8*dc + g)*VP_ST + 8*mkc];
                mma_bf16(o_[dc], pa, vr[q4], vr[q4 + 4], o_[dc]);
            }
        }
    }

    // ---- Normalize ----
    l0 += __shfl_xor_sync(0xffffffffu, l0, 1);
    l0 += __shfl_xor_sync(0xffffffffu, l0, 2);
    l1 += __shfl_xor_sync(0xffffffffu, l1, 1);
    l1 += __shfl_xor_sync(0xffffffffu, l1, 2);
    const float inv0 = 1.0f / l0;
    const float inv1 = 1.0f / l1;

    // ---- Stage O [d][n] fp32 over dead Qs+Kb0 region, write coalesced ----
    __syncthreads();
    float* Os = (float*)su;
    #pragma unroll
    for (int dc = 0; dc < 8; dc++) {
        #pragma unroll
        for (int j = 0; j < 2; j++) {
            int d = 8*dc + 2*q4 + j;
            Os[d*QK_ST + nw + g    ] = o_[dc][j]     * inv0;
            Os[d*QK_ST + nw + g + 8] = o_[dc][2 + j] * inv1;
        }
    }
    __syncthreads();
    const size_t obase = (size_t)bh * 64 * 2048;
    #pragma unroll
    for (int it = 0; it < 32; it++) {
        int lin = it*128 + t;
        int n = lin & 63, d = lin >> 6;
        O[obase + (size_t)d * 2048 + n0 + n] = Os[d*QK_ST + n];
    }
}

// ---------------------------------------------------------------------------
extern "C" void kernel_launch(void* const* d_in, const int* in_sizes, int n_in,
                              void* d_out, int out_size)
{
    const float* desc1 = (const float*)d_in[0];
    const float* desc2 = (const float*)d_in[1];
    const float* wv    = (const float*)d_in[2];
    const float* Wq    = (const float*)d_in[3];
    const float* bq    = (const float*)d_in[4];
    const float* Wk    = (const float*)d_in[5];
    const float* bk    = (const float*)d_in[6];
    const float* Wv    = (const float*)d_in[7];
    const float* bv    = (const float*)d_in[8];
    const float* Wm    = (const float*)d_in[9];
    const float* bm    = (const float*)d_in[10];
    const float* Wc1   = (const float*)d_in[11];
    const float* bc1   = (const float*)d_in[12];
    const float* gamma = (const float*)d_in[13];
    const float* beta  = (const float*)d_in[14];
    const float* mean  = (const float*)d_in[15];
    const float* var   = (const float*)d_in[16];
    const float* Wc2   = (const float*)d_in[17];
    const float* bc2   = (const float*)d_in[18];
    float* out = (float*)d_out;

    uint32_t *qp, *kp, *vp;
    float *attn, *mo, *h;
    cudaGetSymbolAddress((void**)&qp,   g_qp);
    cudaGetSymbolAddress((void**)&kp,   g_kp);
    cudaGetSymbolAddress((void**)&vp,   g_vp);
    cudaGetSymbolAddress((void**)&attn, g_attn);
    cudaGetSymbolAddress((void**)&mo,   g_mo);
    cudaGetSymbolAddress((void**)&h,    g_h);

    cudaFuncSetAttribute(gemm_qkv,    cudaFuncAttributeMaxDynamicSharedMemorySize, GEMM_SMEM);
    cudaFuncSetAttribute(gemm_mma<0>, cudaFuncAttributeMaxDynamicSharedMemorySize, GEMM_SMEM);
    cudaFuncSetAttribute(gemm_mma<2>, cudaFuncAttributeMaxDynamicSharedMemorySize, GEMM_SMEM);
    cudaFuncSetAttribute(gemm_mma<3>, cudaFuncAttributeMaxDynamicSharedMemorySize, GEMM_SMEM);
    cudaFuncSetAttribute(attn_bf16,   cudaFuncAttributeMaxDynamicSharedMemorySize, ATT_SMEM);

    const dim3 blk(128);

    // Fused Q/K/V projections: one launch, z = p*8 + b
    gemm_qkv<<<dim3(N_/128, C_/64, 24), blk, GEMM_SMEM>>>(
        Wq, bq, Wk, bk, Wv, bv, desc1, desc2, wv, qp, kp, vp);

    attn_bf16<<<dim3(N_/64, B_*4), 128, ATT_SMEM>>>(qp, kp, vp, attn);

    const dim3 gp(N_/128, C_/64, B_);
    const dim3 gh(N_/128, 2*C_/64, B_);

    gemm_mma<0><<<gp, blk, GEMM_SMEM>>>(Wm, bm, attn, nullptr, mo, C_, C_, C_,
                                        nullptr, nullptr, nullptr, nullptr);

    gemm_mma<2><<<gh, blk, GEMM_SMEM>>>(Wc1, bc1, desc1, mo, h, 2*C_, 2*C_, C_,
                                        gamma, beta, mean, var);

    gemm_mma<3><<<gp, blk, GEMM_SMEM>>>(Wc2, bc2, h, nullptr, out, C_, 2*C_, 2*C_,
                                        desc1, nullptr, nullptr, nullptr);
}

// round 14
// speedup vs baseline: 2.6698x; 1.0343x over previous
#include <cuda_runtime.h>
#include <cuda_bf16.h>
#include <math.h>
#include <stdint.h>

static constexpr int B_ = 8;
static constexpr int C_ = 256;
static constexpr int N_ = 2048;
static constexpr int M_ = 2048;

// Scratch (no cudaMalloc allowed)
__device__ uint32_t g_qp[B_*4*32*2048];   // packed bf16x2 pairs (d,d+8) per head
__device__ uint32_t g_kp[B_*4*32*2048];
__device__ uint32_t g_vp[B_*4*64*1024];   // packed bf16x2 pairs (m,m+1)
__device__ float    g_attn[B_*C_*N_];
__device__ float    g_mo[B_*C_*N_];
__device__ float    g_h[B_*2*C_*N_];

// ---------------------------------------------------------------------------
// helpers
// ---------------------------------------------------------------------------
__device__ __forceinline__ uint32_t s2u(const void* p) {
    return (uint32_t)__cvta_generic_to_shared(p);
}
#define CPA16(dst, src) \
    asm volatile("cp.async.cg.shared.global [%0], [%1], 16;" :: "r"(dst), "l"(src))
#define CPA_COMMIT() asm volatile("cp.async.commit_group;")
#define CPA_WAIT0()  asm volatile("cp.async.wait_group 0;")
#define CPA_WAIT1()  asm volatile("cp.async.wait_group 1;")

__device__ __forceinline__ void mma_tf32(
    float d[4], const uint32_t a[4], uint32_t b0, uint32_t b1, const float c[4])
{
    asm volatile(
        "mma.sync.aligned.m16n8k8.row.col.f32.tf32.tf32.f32 "
        "{%0,%1,%2,%3}, {%4,%5,%6,%7}, {%8,%9}, {%10,%11,%12,%13};"
        : "=f"(d[0]), "=f"(d[1]), "=f"(d[2]), "=f"(d[3])
        : "r"(a[0]), "r"(a[1]), "r"(a[2]), "r"(a[3]),
          "r"(b0), "r"(b1),
          "f"(c[0]), "f"(c[1]), "f"(c[2]), "f"(c[3]));
}

__device__ __forceinline__ void mma_bf16(
    float d[4], const uint32_t a[4], uint32_t b0, uint32_t b1, const float c[4])
{
    asm volatile(
        "mma.sync.aligned.m16n8k16.row.col.f32.bf16.bf16.f32 "
        "{%0,%1,%2,%3}, {%4,%5,%6,%7}, {%8,%9}, {%10,%11,%12,%13};"
        : "=f"(d[0]), "=f"(d[1]), "=f"(d[2]), "=f"(d[3])
        : "r"(a[0]), "r"(a[1]), "r"(a[2]), "r"(a[3]),
          "r"(b0), "r"(b1),
          "f"(c[0]), "f"(c[1]), "f"(c[2]), "f"(c[3]));
}

__device__ __forceinline__ uint32_t pkbf(float lo, float hi) {
    __nv_bfloat162 h = __floats2bfloat162_rn(lo, hi);
    return *(uint32_t*)&h;
}

// ---------------------------------------------------------------------------
// Shared GEMM tile geometry (64 o x 128 n, K-chunk 32, 2-stage cp.async)
// ---------------------------------------------------------------------------
static constexpr int WG_ST = 36;
static constexpr int XG_ST = 136;
static constexpr int GEMM_SMEM = (2*64*WG_ST + 2*32*XG_ST) * 4;  // 53248 B

// ---------------------------------------------------------------------------
// Fused Q/K/V projection: one launch, blockIdx.z = p*8 + b  (p: 0=Q 1=K 2=V).
// ---------------------------------------------------------------------------
__global__ void __launch_bounds__(128, 4) gemm_qkv(
    const float* __restrict__ Wq, const float* __restrict__ bq,
    const float* __restrict__ Wk, const float* __restrict__ bk,
    const float* __restrict__ Wv, const float* __restrict__ bv,
    const float* __restrict__ desc1, const float* __restrict__ desc2,
    const float* __restrict__ wv,
    uint32_t* __restrict__ qp, uint32_t* __restrict__ kp, uint32_t* __restrict__ vp)
{
    extern __shared__ float sg[];
    float* Wb0 = sg;
    float* Wb1 = sg + 64*WG_ST;
    float* Xb0 = sg + 2*64*WG_ST;
    float* Xb1 = Xb0 + 32*XG_ST;

    const int p  = blockIdx.z >> 3;
    const int b  = blockIdx.z & 7;
    const float* W    = (p == 0) ? Wq : (p == 1) ? Wk : Wv;
    const float* bias = (p == 0) ? bq : (p == 1) ? bk : bv;
    const float* X    = (p == 0) ? desc1 : desc2;
    uint32_t* Yp      = (p == 0) ? qp : (p == 1) ? kp : vp;

    const int o0 = blockIdx.y * 64;
    const int n0 = blockIdx.x * 128;
    const int t  = threadIdx.x;
    const int lane = t & 31, w = t >> 5;
    const int g = lane >> 2, q4 = lane & 3;
    const int ow = (w & 1) * 32;
    const int nwp = (w >> 1) * 64;

    auto issue = [&](int i0, int bufi) {
        float* Wd = bufi ? Wb1 : Wb0;
        float* Xd = bufi ? Xb1 : Xb0;
        #pragma unroll
        for (int r = 0; r < 4; r++) {
            int ch = r*128 + t, row = ch >> 3, c4 = (ch & 7) << 2;
            CPA16(s2u(Wd + row*WG_ST + c4), W + (size_t)(o0 + row) * C_ + i0 + c4);
        }
        #pragma unroll
        for (int r = 0; r < 8; r++) {
            int ch = r*128 + t, row = ch >> 5, c4 = (ch & 31) << 2;
            CPA16(s2u(Xd + row*XG_ST + c4),
                  X + ((size_t)b*C_ + i0 + row) * N_ + n0 + c4);
        }
        CPA_COMMIT();
    };

    float acc[2][8][4];
    #pragma unroll
    for (int st = 0; st < 2; st++)
        #pragma unroll
        for (int nc = 0; nc < 8; nc++)
            #pragma unroll
            for (int j = 0; j < 4; j++) acc[st][nc][j] = 0.f;

    issue(0, 0);
    for (int i = 0; i < C_/32; i++) {
        CPA_WAIT0();
        __syncthreads();
        if (i + 1 < C_/32) issue((i + 1) << 5, (i + 1) & 1);

        const float* Wc = (i & 1) ? Wb1 : Wb0;
        const float* Xc = (i & 1) ? Xb1 : Xb0;

        #pragma unroll
        for (int s = 0; s < 4; s++) {
            uint32_t a2r[2][4];
            #pragma unroll
            for (int st = 0; st < 2; st++) {
                const float* wr0 = &Wc[(ow + 16*st + g    )*WG_ST + 8*s + q4];
                const float* wr1 = &Wc[(ow + 16*st + g + 8)*WG_ST + 8*s + q4];
                a2r[st][0] = __float_as_uint(wr0[0]);
                a2r[st][1] = __float_as_uint(wr1[0]);
                a2r[st][2] = __float_as_uint(wr0[4]);
                a2r[st][3] = __float_as_uint(wr1[4]);
            }
            const float* x0 = &Xc[(8*s + q4    )*XG_ST + nwp + g];
            const float* x1 = &Xc[(8*s + q4 + 4)*XG_ST + nwp + g];
            #pragma unroll
            for (int nc = 0; nc < 8; nc++) {
                uint32_t b0 = __float_as_uint(x0[8*nc]);
                uint32_t b1 = __float_as_uint(x1[8*nc]);
                mma_tf32(acc[0][nc], a2r[0], b0, b1, acc[0][nc]);
                mma_tf32(acc[1][nc], a2r[1], b0, b1, acc[1][nc]);
            }
        }
    }

    // ---- Epilogue: pack ----
    #pragma unroll
    for (int st = 0; st < 2; st++) {
        const int row0 = o0 + ow + 16*st + g;
        const int row1 = row0 + 8;
        const float bi0 = bias[row0];
        const float bi1 = bias[row1];
        const int d0 = row0 & 63, h = row0 >> 6;

        if (p < 2) {
            const size_t obase =
                (((size_t)b*4 + h)*32 + ((d0 >> 4)*8 + (d0 & 7))) * (size_t)N_;
            #pragma unroll
            for (int nc = 0; nc < 8; nc++) {
                const int n = n0 + nwp + 8*nc + 2*q4;
                Yp[obase + n    ] = pkbf(acc[st][nc][0] + bi0, acc[st][nc][2] + bi1);
                Yp[obase + n + 1] = pkbf(acc[st][nc][1] + bi0, acc[st][nc][3] + bi1);
            }
        } else {
            const size_t b0v = (((size_t)b*4 + h)*64 + d0    ) * (size_t)(N_/2);
            const size_t b1v = (((size_t)b*4 + h)*64 + d0 + 8) * (size_t)(N_/2);
            #pragma unroll
            for (int nc = 0; nc < 8; nc++) {
                const int n = n0 + nwp + 8*nc + 2*q4;
                float2 wv2 = *(const float2*)&wv[(size_t)b * N_ + n];
                Yp[b0v + (n >> 1)] = pkbf((acc[st][nc][0] + bi0) * wv2.x,
                                          (acc[st][nc][1] + bi0) * wv2.y);
                Yp[b1v + (n >> 1)] = pkbf((acc[st][nc][2] + bi1) * wv2.x,
                                          (acc[st][nc][3] + bi1) * wv2.y);
            }
        }
    }
}

// ---------------------------------------------------------------------------
// General tensor-core GEMM (tf32) with fused epilogue — Wm / Wc1 / Wc2.
// MODE 0:+bias  2:BN+ReLU  3:+residual ; concat via Ca.
// ---------------------------------------------------------------------------
template<int MODE>
__global__ void __launch_bounds__(128, 4) gemm_mma(
    const float* __restrict__ W, const float* __restrict__ bias,
    const float* __restrict__ Xa, const float* __restrict__ Xb,
    float* __restrict__ Y, int Cout, int Cin, int Ca,
    const float* __restrict__ e0, const float* __restrict__ e1,
    const float* __restrict__ e2, const float* __restrict__ e3)
{
    extern __shared__ float sg[];
    float* Wb0 = sg;
    float* Wb1 = sg + 64*WG_ST;
    float* Xb0 = sg + 2*64*WG_ST;
    float* Xb1 = Xb0 + 32*XG_ST;

    const int b  = blockIdx.z;
    const int o0 = blockIdx.y * 64;
    const int n0 = blockIdx.x * 128;
    const int t  = threadIdx.x;
    const int lane = t & 31, w = t >> 5;
    const int g = lane >> 2, q4 = lane & 3;
    const int ow = (w & 1) * 32;
    const int nwp = (w >> 1) * 64;
    const int Cb = Cin - Ca;

    auto issue = [&](int i0, int bufi) {
        float* Wd = bufi ? Wb1 : Wb0;
        float* Xd = bufi ? Xb1 : Xb0;
        #pragma unroll
        for (int r = 0; r < 4; r++) {
            int ch = r*128 + t, row = ch >> 3, c4 = (ch & 7) << 2;
            CPA16(s2u(Wd + row*WG_ST + c4), W + (size_t)(o0 + row) * Cin + i0 + c4);
        }
        #pragma unroll
        for (int r = 0; r < 8; r++) {
            int ch = r*128 + t, row = ch >> 5, c4 = (ch & 31) << 2;
            int ig = i0 + row;
            const float* src = (ig < Ca)
                ? Xa + ((size_t)b*Ca + ig) * N_ + n0 + c4
                : Xb + ((size_t)b*Cb + (ig - Ca)) * N_ + n0 + c4;
            CPA16(s2u(Xd + row*XG_ST + c4), src);
        }
        CPA_COMMIT();
    };

    float acc[2][8][4];
    #pragma unroll
    for (int st = 0; st < 2; st++)
        #pragma unroll
        for (int nc = 0; nc < 8; nc++)
            #pragma unroll
            for (int j = 0; j < 4; j++) acc[st][nc][j] = 0.f;

    const int nch = Cin >> 5;
    issue(0, 0);
    for (int i = 0; i < nch; i++) {
        CPA_WAIT0();
        __syncthreads();
        if (i + 1 < nch) issue((i + 1) << 5, (i + 1) & 1);

        const float* Wc = (i & 1) ? Wb1 : Wb0;
        const float* Xc = (i & 1) ? Xb1 : Xb0;

        #pragma unroll
        for (int s = 0; s < 4; s++) {
            uint32_t a2r[2][4];
            #pragma unroll
            for (int st = 0; st < 2; st++) {
                const float* wr0 = &Wc[(ow + 16*st + g    )*WG_ST + 8*s + q4];
                const float* wr1 = &Wc[(ow + 16*st + g + 8)*WG_ST + 8*s + q4];
                a2r[st][0] = __float_as_uint(wr0[0]);
                a2r[st][1] = __float_as_uint(wr1[0]);
                a2r[st][2] = __float_as_uint(wr0[4]);
                a2r[st][3] = __float_as_uint(wr1[4]);
            }
            const float* x0 = &Xc[(8*s + q4    )*XG_ST + nwp + g];
            const float* x1 = &Xc[(8*s + q4 + 4)*XG_ST + nwp + g];
            #pragma unroll
            for (int nc = 0; nc < 8; nc++) {
                uint32_t b0 = __float_as_uint(x0[8*nc]);
                uint32_t b1 = __float_as_uint(x1[8*nc]);
                mma_tf32(acc[0][nc], a2r[0], b0, b1, acc[0][nc]);
                mma_tf32(acc[1][nc], a2r[1], b0, b1, acc[1][nc]);
            }
        }
    }

    #pragma unroll
    for (int st = 0; st < 2; st++) {
        const int row0 = o0 + ow + 16*st + g;
        const int row1 = row0 + 8;
        const float bi0 = bias[row0];
        const float bi1 = bias[row1];
        float inv0, add0, inv1, add1;
        if constexpr (MODE == 2) {
            inv0 = e0[row0] * rsqrtf(e3[row0] + 1e-5f);
            add0 = e1[row0] - e2[row0] * inv0;
            inv1 = e0[row1] * rsqrtf(e3[row1] + 1e-5f);
            add1 = e1[row1] - e2[row1] * inv1;
        }
        const size_t yb0 = ((size_t)b*Cout + row0) * N_;
        const size_t yb1 = ((size_t)b*Cout + row1) * N_;
        #pragma unroll
        for (int nc = 0; nc < 8; nc++) {
            const int n = n0 + nwp + 8*nc + 2*q4;
            float2 y0 = make_float2(acc[st][nc][0] + bi0, acc[st][nc][1] + bi0);
            float2 y1 = make_float2(acc[st][nc][2] + bi1, acc[st][nc][3] + bi1);
            if constexpr (MODE == 2) {
                y0.x = fmaxf(fmaf(y0.x, inv0, add0), 0.f);
                y0.y = fmaxf(fmaf(y0.y, inv0, add0), 0.f);
                y1.x = fmaxf(fmaf(y1.x, inv1, add1), 0.f);
                y1.y = fmaxf(fmaf(y1.y, inv1, add1), 0.f);
            }
            if constexpr (MODE == 3) {
                float2 r0 = *(const float2*)&e0[yb0 + n];
                float2 r1 = *(const float2*)&e0[yb1 + n];
                y0.x += r0.x; y0.y += r0.y;
                y1.x += r1.x; y1.y += r1.y;
            }
            *(float2*)&Y[yb0 + n] = y0;
            *(float2*)&Y[yb1 + n] = y1;
        }
    }
}

// ---------------------------------------------------------------------------
// Attention, bf16 mma, register-resident P, 32 Q-rows per warp (2 strips).
// CTA 128 thr / 4 warps, n-tile 128; K/V fragments shared across strips.
// QP/KP: [bh][32 dp][2048] u32 ; VP: [bh][64 d][1024] u32.
// smem (u32): Qs 32x136 | Kb0,Kb1 32x72 | Vb0,Vb1 64x36
// ---------------------------------------------------------------------------
static constexpr int QS_ST = 136;  // u32 (n-tile 128 + pad 8)
static constexpr int KK_ST = 72;   // u32
static constexpr int VP_ST = 36;   // u32
static constexpr int ATT_SMEM = (32*QS_ST + 2*32*KK_ST + 2*64*VP_ST) * 4;  // 54272 B

__global__ void __launch_bounds__(128) attn_bf16(
    const uint32_t* __restrict__ QP, const uint32_t* __restrict__ KP,
    const uint32_t* __restrict__ VP, float* __restrict__ O)
{
    extern __shared__ uint32_t su[];
    uint32_t* Qs  = su;                       // 4352
    uint32_t* Kb0 = su + 4352;                // 2304
    uint32_t* Kb1 = su + 6656;
    uint32_t* Vb0 = su + 8960;                // 2304
    uint32_t* Vb1 = su + 11264;

    const int bh = blockIdx.y;
    const int n0 = blockIdx.x * 128;
    const size_t qkb = (size_t)bh * 32 * 2048;
    const size_t vb  = (size_t)bh * 64 * 1024;
    const int t = threadIdx.x;
    const int lane = t & 31, w = t >> 5;
    const int g = lane >> 2, q4 = lane & 3;
    const int nw = w * 32;   // warp owns rows [nw, nw+32): strips nw, nw+16

    auto issue_kv = [&](int m0, int bufi) {
        uint32_t* Kd = bufi ? Kb1 : Kb0;
        uint32_t* Vd = bufi ? Vb1 : Vb0;
        #pragma unroll
        for (int r = 0; r < 4; r++) {
            int ch = r*128 + t, row = ch >> 4, c4 = (ch & 15) << 2;
            CPA16(s2u(Kd + row*KK_ST + c4), KP + qkb + (size_t)row*2048 + m0 + c4);
        }
        #pragma unroll
        for (int r = 0; r < 4; r++) {
            int ch = r*128 + t, row = ch >> 3, c4 = (ch & 7) << 2;
            CPA16(s2u(Vd + row*VP_ST + c4), VP + vb + (size_t)row*1024 + (m0 >> 1) + c4);
        }
        CPA_COMMIT();
    };

    // Prologue: Q (group 0), KV tile 0 (group 1)
    #pragma unroll
    for (int r = 0; r < 8; r++) {
        int ch = r*128 + t, row = ch >> 5, c4 = (ch & 31) << 2;
        CPA16(s2u(Qs + row*QS_ST + c4), QP + qkb + (size_t)row*2048 + n0 + c4);
    }
    CPA_COMMIT();
    issue_kv(0, 0);
    CPA_WAIT1();
    __syncthreads();

    // Q A-fragments for both strips
    uint32_t qa[2][4][4];
    #pragma unroll
    for (int st = 0; st < 2; st++) {
        const int nb = nw + 16*st;
        #pragma unroll
        for (int dc = 0; dc < 4; dc++) {
            qa[st][dc][0] = Qs[(8*dc + q4    )*QS_ST + nb + g];
            qa[st][dc][1] = Qs[(8*dc + q4    )*QS_ST + nb + g + 8];
            qa[st][dc][2] = Qs[(8*dc + q4 + 4)*QS_ST + nb + g];
            qa[st][dc][3] = Qs[(8*dc + q4 + 4)*QS_ST + nb + g + 8];
        }
    }

    float o0_[8][4], o1_[8][4];
    #pragma unroll
    for (int dc = 0; dc < 8; dc++)
        #pragma unroll
        for (int j = 0; j < 4; j++) { o0_[dc][j] = 0.f; o1_[dc][j] = 0.f; }
    float l00 = 0.f, l01 = 0.f, l10 = 0.f, l11 = 0.f;

    for (int i = 0; i < M_/64; i++) {
        CPA_WAIT0();
        __syncthreads();
        if (i + 1 < M_/64) issue_kv((i + 1) * 64, (i + 1) & 1);

        const uint32_t* Kc = (i & 1) ? Kb1 : Kb0;
        const uint32_t* Vc = (i & 1) ? Vb1 : Vb0;

        // ---- S = Q^T K for both strips (K fragments loaded once) ----
        float s0[8][4], s1[8][4];
        #pragma unroll
        for (int mc = 0; mc < 8; mc++)
            #pragma unroll
            for (int j = 0; j < 4; j++) { s0[mc][j] = 0.f; s1[mc][j] = 0.f; }

        #pragma unroll
        for (int dc = 0; dc < 4; dc++) {
            const uint32_t* k0 = &Kc[(8*dc + q4    )*KK_ST + g];
            const uint32_t* k1 = &Kc[(8*dc + q4 + 4)*KK_ST + g];
            #pragma unroll
            for (int mc = 0; mc < 8; mc++) {
                uint32_t b0 = k0[8*mc], b1 = k1[8*mc];
                mma_bf16(s0[mc], qa[0][dc], b0, b1, s0[mc]);
                mma_bf16(s1[mc], qa[1][dc], b0, b1, s1[mc]);
            }
        }

        // ---- P = exp(S/8); row sums; pack to register A-fragments ----
        uint32_t pa0[4][4], pa1[4][4];
        #pragma unroll
        for (int mc = 0; mc < 8; mc++) {
            s0[mc][0] = __expf(s0[mc][0] * 0.125f);
            s0[mc][1] = __expf(s0[mc][1] * 0.125f);
            s0[mc][2] = __expf(s0[mc][2] * 0.125f);
            s0[mc][3] = __expf(s0[mc][3] * 0.125f);
            l00 += s0[mc][0] + s0[mc][1];
            l01 += s0[mc][2] + s0[mc][3];
            s1[mc][0] = __expf(s1[mc][0] * 0.125f);
            s1[mc][1] = __expf(s1[mc][1] * 0.125f);
            s1[mc][2] = __expf(s1[mc][2] * 0.125f);
            s1[mc][3] = __expf(s1[mc][3] * 0.125f);
            l10 += s1[mc][0] + s1[mc][1];
            l11 += s1[mc][2] + s1[mc][3];
        }
        #pragma unroll
        for (int mkc = 0; mkc < 4; mkc++) {
            pa0[mkc][0] = pkbf(s0[2*mkc  ][0], s0[2*mkc  ][1]);
            pa0[mkc][1] = pkbf(s0[2*mkc  ][2], s0[2*mkc  ][3]);
            pa0[mkc][2] = pkbf(s0[2*mkc+1][0], s0[2*mkc+1][1]);
            pa0[mkc][3] = pkbf(s0[2*mkc+1][2], s0[2*mkc+1][3]);
            pa1[mkc][0] = pkbf(s1[2*mkc  ][0], s1[2*mkc  ][1]);
            pa1[mkc][1] = pkbf(s1[2*mkc  ][2], s1[2*mkc  ][3]);
            pa1[mkc][2] = pkbf(s1[2*mkc+1][0], s1[2*mkc+1][1]);
            pa1[mkc][3] = pkbf(s1[2*mkc+1][2], s1[2*mkc+1][3]);
        }

        // ---- O += P V (V fragments loaded once, feed both strips) ----
        #pragma unroll
        for (int mkc = 0; mkc < 4; mkc++) {
            #pragma unroll
            for (int dc = 0; dc < 8; dc++) {
                const uint32_t* vr = &Vc[(8*dc + g)*VP_ST + 8*mkc];
                uint32_t v0 = vr[q4], v1 = vr[q4 + 4];
                mma_bf16(o0_[dc], pa0[mkc], v0, v1, o0_[dc]);
                mma_bf16(o1_[dc], pa1[mkc], v0, v1, o1_[dc]);
            }
        }
    }

    // ---- Normalize ----
    l00 += __shfl_xor_sync(0xffffffffu, l00, 1);
    l00 += __shfl_xor_sync(0xffffffffu, l00, 2);
    l01 += __shfl_xor_sync(0xffffffffu, l01, 1);
    l01 += __shfl_xor_sync(0xffffffffu, l01, 2);
    l10 += __shfl_xor_sync(0xffffffffu, l10, 1);
    l10 += __shfl_xor_sync(0xffffffffu, l10, 2);
    l11 += __shfl_xor_sync(0xffffffffu, l11, 1);
    l11 += __shfl_xor_sync(0xffffffffu, l11, 2);
    const float i00 = 1.0f / l00, i01 = 1.0f / l01;
    const float i10 = 1.0f / l10, i11 = 1.0f / l11;

    // ---- Stage O [64 d][128 n] fp32 over dead smem, write coalesced ----
    __syncthreads();
    float* Os = (float*)su;          // 64*136 floats = 34816 B <= 54272 B
    #pragma unroll
    for (int dc = 0; dc < 8; dc++) {
        #pragma unroll
        for (int j = 0; j < 2; j++) {
            int d = 8*dc + 2*q4 + j;
            Os[d*QS_ST + nw + g         ] = o0_[dc][j]     * i00;
            Os[d*QS_ST + nw + g + 8     ] = o0_[dc][2 + j] * i01;
            Os[d*QS_ST + nw + 16 + g    ] = o1_[dc][j]     * i10;
            Os[d*QS_ST + nw + 16 + g + 8] = o1_[dc][2 + j] * i11;
        }
    }
    __syncthreads();
    const size_t obase = (size_t)bh * 64 * 2048;
    #pragma unroll
    for (int d = 0; d < 64; d++) {
        O[obase + (size_t)d * 2048 + n0 + t] = Os[d*QS_ST + t];
    }
}

// ---------------------------------------------------------------------------
extern "C" void kernel_launch(void* const* d_in, const int* in_sizes, int n_in,
                              void* d_out, int out_size)
{
    const float* desc1 = (const float*)d_in[0];
    const float* desc2 = (const float*)d_in[1];
    const float* wv    = (const float*)d_in[2];
    const float* Wq    = (const float*)d_in[3];
    const float* bq    = (const float*)d_in[4];
    const float* Wk    = (const float*)d_in[5];
    const float* bk    = (const float*)d_in[6];
    const float* Wv    = (const float*)d_in[7];
    const float* bv    = (const float*)d_in[8];
    const float* Wm    = (const float*)d_in[9];
    const float* bm    = (const float*)d_in[10];
    const float* Wc1   = (const float*)d_in[11];
    const float* bc1   = (const float*)d_in[12];
    const float* gamma = (const float*)d_in[13];
    const float* beta  = (const float*)d_in[14];
    const float* mean  = (const float*)d_in[15];
    const float* var   = (const float*)d_in[16];
    const float* Wc2   = (const float*)d_in[17];
    const float* bc2   = (const float*)d_in[18];
    float* out = (float*)d_out;

    uint32_t *qp, *kp, *vp;
    float *attn, *mo, *h;
    cudaGetSymbolAddress((void**)&qp,   g_qp);
    cudaGetSymbolAddress((void**)&kp,   g_kp);
    cudaGetSymbolAddress((void**)&vp,   g_vp);
    cudaGetSymbolAddress((void**)&attn, g_attn);
    cudaGetSymbolAddress((void**)&mo,   g_mo);
    cudaGetSymbolAddress((void**)&h,    g_h);

    cudaFuncSetAttribute(gemm_qkv,    cudaFuncAttributeMaxDynamicSharedMemorySize, GEMM_SMEM);
    cudaFuncSetAttribute(gemm_mma<0>, cudaFuncAttributeMaxDynamicSharedMemorySize, GEMM_SMEM);
    cudaFuncSetAttribute(gemm_mma<2>, cudaFuncAttributeMaxDynamicSharedMemorySize, GEMM_SMEM);
    cudaFuncSetAttribute(gemm_mma<3>, cudaFuncAttributeMaxDynamicSharedMemorySize, GEMM_SMEM);
    cudaFuncSetAttribute(attn_bf16,   cudaFuncAttributeMaxDynamicSharedMemorySize, ATT_SMEM);

    const dim3 blk(128);

    // Fused Q/K/V projections: one launch, z = p*8 + b
    gemm_qkv<<<dim3(N_/128, C_/64, 24), blk, GEMM_SMEM>>>(
        Wq, bq, Wk, bk, Wv, bv, desc1, desc2, wv, qp, kp, vp);

    // Attention: n-tile 128, 4 warps x 32 rows
    attn_bf16<<<dim3(N_/128, B_*4), 128, ATT_SMEM>>>(qp, kp, vp, attn);

    const dim3 gp(N_/128, C_/64, B_);
    const dim3 gh(N_/128, 2*C_/64, B_);

    gemm_mma<0><<<gp, blk, GEMM_SMEM>>>(Wm, bm, attn, nullptr, mo, C_, C_, C_,
                                        nullptr, nullptr, nullptr, nullptr);

    gemm_mma<2><<<gh, blk, GEMM_SMEM>>>(Wc1, bc1, desc1, mo, h, 2*C_, 2*C_, C_,
                                        gamma, beta, mean, var);

    gemm_mma<3><<<gp, blk, GEMM_SMEM>>>(Wc2, bc2, h, nullptr, out, C_, 2*C_, 2*C_,
                                        desc1, nullptr, nullptr, nullptr);
}

// round 15
// speedup vs baseline: 2.6861x; 1.0061x over previous
#include <cuda_runtime.h>
#include <cuda_bf16.h>
#include <math.h>
#include <stdint.h>

static constexpr int B_ = 8;
static constexpr int C_ = 256;
static constexpr int N_ = 2048;
static constexpr int M_ = 2048;

// Scratch (no cudaMalloc allowed)
__device__ uint32_t g_qp[B_*4*32*2048];   // packed bf16x2 pairs (d,d+8) per head
__device__ uint32_t g_kp[B_*4*32*2048];
__device__ uint32_t g_vp[B_*4*64*1024];   // packed bf16x2 pairs (m,m+1)
__device__ float    g_attn[B_*C_*N_];
__device__ float    g_h[B_*2*C_*N_];
__device__ float    g_wf[2*C_*2*C_];      // fused Wc1' = [Wc1a, Wc1b@Wm]
__device__ float    g_bf[2*C_];           // fused bias = bc1 + Wc1b@bm

// ---------------------------------------------------------------------------
// helpers
// ---------------------------------------------------------------------------
__device__ __forceinline__ uint32_t s2u(const void* p) {
    return (uint32_t)__cvta_generic_to_shared(p);
}
#define CPA16(dst, src) \
    asm volatile("cp.async.cg.shared.global [%0], [%1], 16;" :: "r"(dst), "l"(src))
#define CPA_COMMIT() asm volatile("cp.async.commit_group;")
#define CPA_WAIT0()  asm volatile("cp.async.wait_group 0;")
#define CPA_WAIT1()  asm volatile("cp.async.wait_group 1;")

__device__ __forceinline__ void mma_tf32(
    float d[4], const uint32_t a[4], uint32_t b0, uint32_t b1, const float c[4])
{
    asm volatile(
        "mma.sync.aligned.m16n8k8.row.col.f32.tf32.tf32.f32 "
        "{%0,%1,%2,%3}, {%4,%5,%6,%7}, {%8,%9}, {%10,%11,%12,%13};"
        : "=f"(d[0]), "=f"(d[1]), "=f"(d[2]), "=f"(d[3])
        : "r"(a[0]), "r"(a[1]), "r"(a[2]), "r"(a[3]),
          "r"(b0), "r"(b1),
          "f"(c[0]), "f"(c[1]), "f"(c[2]), "f"(c[3]));
}

__device__ __forceinline__ void mma_bf16(
    float d[4], const uint32_t a[4], uint32_t b0, uint32_t b1, const float c[4])
{
    asm volatile(
        "mma.sync.aligned.m16n8k16.row.col.f32.bf16.bf16.f32 "
        "{%0,%1,%2,%3}, {%4,%5,%6,%7}, {%8,%9}, {%10,%11,%12,%13};"
        : "=f"(d[0]), "=f"(d[1]), "=f"(d[2]), "=f"(d[3])
        : "r"(a[0]), "r"(a[1]), "r"(a[2]), "r"(a[3]),
          "r"(b0), "r"(b1),
          "f"(c[0]), "f"(c[1]), "f"(c[2]), "f"(c[3]));
}

__device__ __forceinline__ uint32_t pkbf(float lo, float hi) {
    __nv_bfloat162 h = __floats2bfloat162_rn(lo, hi);
    return *(uint32_t*)&h;
}

// ---------------------------------------------------------------------------
// Shared GEMM tile geometry (64 o x 128 n, K-chunk 32, 2-stage cp.async)
// ---------------------------------------------------------------------------
static constexpr int WG_ST = 36;
static constexpr int XG_ST = 136;
static constexpr int GEMM_SMEM = (2*64*WG_ST + 2*32*XG_ST) * 4;  // 53248 B

// ---------------------------------------------------------------------------
// Fused Q/K/V projection + Wm-fusion prep, one launch.
// blockIdx.z in [0,24): p = z>>3 (0=Q 1=K 2=V), b = z&7.
// blockIdx.z == 24: prep slice —
//   CTA id 0..15 : Wf[:,256:512] = Wc1[:,256:] @ Wm   (tensor GEMM tiles)
//   CTA id 16..47: Wf[:,0:256] copy + bf = bc1 + Wc1[:,256:]@bm (16 rows each)
// ---------------------------------------------------------------------------
__global__ void __launch_bounds__(128, 4) gemm_qkv(
    const float* __restrict__ Wq, const float* __restrict__ bq,
    const float* __restrict__ Wk, const float* __restrict__ bk,
    const float* __restrict__ Wv, const float* __restrict__ bv,
    const float* __restrict__ desc1, const float* __restrict__ desc2,
    const float* __restrict__ wv,
    uint32_t* __restrict__ qp, uint32_t* __restrict__ kp, uint32_t* __restrict__ vp,
    const float* __restrict__ Wc1, const float* __restrict__ bc1,
    const float* __restrict__ Wm,  const float* __restrict__ bm,
    float* __restrict__ Wf, float* __restrict__ bf)
{
    extern __shared__ float sg[];
    float* Wb0 = sg;
    float* Wb1 = sg + 64*WG_ST;
    float* Xb0 = sg + 2*64*WG_ST;
    float* Xb1 = Xb0 + 32*XG_ST;

    const int t  = threadIdx.x;
    const int lane = t & 31, w = t >> 5;
    const int g = lane >> 2, q4 = lane & 3;
    const int ow = (w & 1) * 32;
    const int nwp = (w >> 1) * 64;

    // ======================= PREP SLICE (z == 24) =======================
    if (blockIdx.z == 24) {
        const int cid = blockIdx.y * gridDim.x + blockIdx.x;  // 0..63
        if (cid < 16) {
            // ---- Wf2 = Wc1b @ Wm : tile o0 x i0, 64 x 128, K = 256 ----
            const int o0 = (cid >> 1) * 64;
            const int i0 = (cid & 1) * 128;

            auto issueP = [&](int k0, int bufi) {
                float* Wd = bufi ? Wb1 : Wb0;
                float* Xd = bufi ? Xb1 : Xb0;
                #pragma unroll
                for (int r = 0; r < 4; r++) {
                    int ch = r*128 + t, row = ch >> 3, c4 = (ch & 7) << 2;
                    CPA16(s2u(Wd + row*WG_ST + c4),
                          Wc1 + (size_t)(o0 + row) * 512 + 256 + k0 + c4);
                }
                #pragma unroll
                for (int r = 0; r < 8; r++) {
                    int ch = r*128 + t, row = ch >> 5, c4 = (ch & 31) << 2;
                    CPA16(s2u(Xd + row*XG_ST + c4),
                          Wm + (size_t)(k0 + row) * 256 + i0 + c4);
                }
                CPA_COMMIT();
            };

            float acc[2][8][4];
            #pragma unroll
            for (int st = 0; st < 2; st++)
                #pragma unroll
                for (int nc = 0; nc < 8; nc++)
                    #pragma unroll
                    for (int j = 0; j < 4; j++) acc[st][nc][j] = 0.f;

            issueP(0, 0);
            for (int i = 0; i < 8; i++) {
                CPA_WAIT0();
                __syncthreads();
                if (i + 1 < 8) issueP((i + 1) << 5, (i + 1) & 1);
                const float* Wc = (i & 1) ? Wb1 : Wb0;
                const float* Xc = (i & 1) ? Xb1 : Xb0;
                #pragma unroll
                for (int s = 0; s < 4; s++) {
                    uint32_t a2r[2][4];
                    #pragma unroll
                    for (int st = 0; st < 2; st++) {
                        const float* wr0 = &Wc[(ow + 16*st + g    )*WG_ST + 8*s + q4];
                        const float* wr1 = &Wc[(ow + 16*st + g + 8)*WG_ST + 8*s + q4];
                        a2r[st][0] = __float_as_uint(wr0[0]);
                        a2r[st][1] = __float_as_uint(wr1[0]);
                        a2r[st][2] = __float_as_uint(wr0[4]);
                        a2r[st][3] = __float_as_uint(wr1[4]);
                    }
                    const float* x0 = &Xc[(8*s + q4    )*XG_ST + nwp + g];
                    const float* x1 = &Xc[(8*s + q4 + 4)*XG_ST + nwp + g];
                    #pragma unroll
                    for (int nc = 0; nc < 8; nc++) {
                        uint32_t b0 = __float_as_uint(x0[8*nc]);
                        uint32_t b1 = __float_as_uint(x1[8*nc]);
                        mma_tf32(acc[0][nc], a2r[0], b0, b1, acc[0][nc]);
                        mma_tf32(acc[1][nc], a2r[1], b0, b1, acc[1][nc]);
                    }
                }
            }
            #pragma unroll
            for (int st = 0; st < 2; st++) {
                const int row0 = o0 + ow + 16*st + g;
                const int row1 = row0 + 8;
                #pragma unroll
                for (int nc = 0; nc < 8; nc++) {
                    const int n = i0 + nwp + 8*nc + 2*q4;
                    *(float2*)&Wf[(size_t)row0*512 + 256 + n] =
                        make_float2(acc[st][nc][0], acc[st][nc][1]);
                    *(float2*)&Wf[(size_t)row1*512 + 256 + n] =
                        make_float2(acc[st][nc][2], acc[st][nc][3]);
                }
            }
        } else if (cid < 48) {
            // ---- copy Wc1a -> Wf[:,0:256]; bf = bc1 + Wc1b @ bm ----
            __shared__ float red[4];
            const int row0 = (cid - 16) * 16;
            for (int r = 0; r < 16; r++) {
                const int row = row0 + r;
                const size_t rb = (size_t)row * 512;
                Wf[rb + t]       = Wc1[rb + t];
                Wf[rb + 128 + t] = Wc1[rb + 128 + t];
                float p = Wc1[rb + 256 + t] * bm[t]
                        + Wc1[rb + 384 + t] * bm[128 + t];
                p += __shfl_xor_sync(0xffffffffu, p, 1);
                p += __shfl_xor_sync(0xffffffffu, p, 2);
                p += __shfl_xor_sync(0xffffffffu, p, 4);
                p += __shfl_xor_sync(0xffffffffu, p, 8);
                p += __shfl_xor_sync(0xffffffffu, p, 16);
                if (lane == 0) red[w] = p;
                __syncthreads();
                if (t == 0) bf[row] = bc1[row] + red[0] + red[1] + red[2] + red[3];
                __syncthreads();
            }
        }
        return;
    }

    // ======================= Q/K/V PROJECTIONS =======================
    const int p  = blockIdx.z >> 3;
    const int b  = blockIdx.z & 7;
    const float* W    = (p == 0) ? Wq : (p == 1) ? Wk : Wv;
    const float* bias = (p == 0) ? bq : (p == 1) ? bk : bv;
    const float* X    = (p == 0) ? desc1 : desc2;
    uint32_t* Yp      = (p == 0) ? qp : (p == 1) ? kp : vp;

    const int o0 = blockIdx.y * 64;
    const int n0 = blockIdx.x * 128;

    auto issue = [&](int i0, int bufi) {
        float* Wd = bufi ? Wb1 : Wb0;
        float* Xd = bufi ? Xb1 : Xb0;
        #pragma unroll
        for (int r = 0; r < 4; r++) {
            int ch = r*128 + t, row = ch >> 3, c4 = (ch & 7) << 2;
            CPA16(s2u(Wd + row*WG_ST + c4), W + (size_t)(o0 + row) * C_ + i0 + c4);
        }
        #pragma unroll
        for (int r = 0; r < 8; r++) {
            int ch = r*128 + t, row = ch >> 5, c4 = (ch & 31) << 2;
            CPA16(s2u(Xd + row*XG_ST + c4),
                  X + ((size_t)b*C_ + i0 + row) * N_ + n0 + c4);
        }
        CPA_COMMIT();
    };

    float acc[2][8][4];
    #pragma unroll
    for (int st = 0; st < 2; st++)
        #pragma unroll
        for (int nc = 0; nc < 8; nc++)
            #pragma unroll
            for (int j = 0; j < 4; j++) acc[st][nc][j] = 0.f;

    issue(0, 0);
    for (int i = 0; i < C_/32; i++) {
        CPA_WAIT0();
        __syncthreads();
        if (i + 1 < C_/32) issue((i + 1) << 5, (i + 1) & 1);

        const float* Wc = (i & 1) ? Wb1 : Wb0;
        const float* Xc = (i & 1) ? Xb1 : Xb0;

        #pragma unroll
        for (int s = 0; s < 4; s++) {
            uint32_t a2r[2][4];
            #pragma unroll
            for (int st = 0; st < 2; st++) {
                const float* wr0 = &Wc[(ow + 16*st + g    )*WG_ST + 8*s + q4];
                const float* wr1 = &Wc[(ow + 16*st + g + 8)*WG_ST + 8*s + q4];
                a2r[st][0] = __float_as_uint(wr0[0]);
                a2r[st][1] = __float_as_uint(wr1[0]);
                a2r[st][2] = __float_as_uint(wr0[4]);
                a2r[st][3] = __float_as_uint(wr1[4]);
            }
            const float* x0 = &Xc[(8*s + q4    )*XG_ST + nwp + g];
            const float* x1 = &Xc[(8*s + q4 + 4)*XG_ST + nwp + g];
            #pragma unroll
            for (int nc = 0; nc < 8; nc++) {
                uint32_t b0 = __float_as_uint(x0[8*nc]);
                uint32_t b1 = __float_as_uint(x1[8*nc]);
                mma_tf32(acc[0][nc], a2r[0], b0, b1, acc[0][nc]);
                mma_tf32(acc[1][nc], a2r[1], b0, b1, acc[1][nc]);
            }
        }
    }

    // ---- Epilogue: pack ----
    #pragma unroll
    for (int st = 0; st < 2; st++) {
        const int row0 = o0 + ow + 16*st + g;
        const int row1 = row0 + 8;
        const float bi0 = bias[row0];
        const float bi1 = bias[row1];
        const int d0 = row0 & 63, h = row0 >> 6;

        if (p < 2) {
            const size_t obase =
                (((size_t)b*4 + h)*32 + ((d0 >> 4)*8 + (d0 & 7))) * (size_t)N_;
            #pragma unroll
            for (int nc = 0; nc < 8; nc++) {
                const int n = n0 + nwp + 8*nc + 2*q4;
                Yp[obase + n    ] = pkbf(acc[st][nc][0] + bi0, acc[st][nc][2] + bi1);
                Yp[obase + n + 1] = pkbf(acc[st][nc][1] + bi0, acc[st][nc][3] + bi1);
            }
        } else {
            const size_t b0v = (((size_t)b*4 + h)*64 + d0    ) * (size_t)(N_/2);
            const size_t b1v = (((size_t)b*4 + h)*64 + d0 + 8) * (size_t)(N_/2);
            #pragma unroll
            for (int nc = 0; nc < 8; nc++) {
                const int n = n0 + nwp + 8*nc + 2*q4;
                float2 wv2 = *(const float2*)&wv[(size_t)b * N_ + n];
                Yp[b0v + (n >> 1)] = pkbf((acc[st][nc][0] + bi0) * wv2.x,
                                          (acc[st][nc][1] + bi0) * wv2.y);
                Yp[b1v + (n >> 1)] = pkbf((acc[st][nc][2] + bi1) * wv2.x,
                                          (acc[st][nc][3] + bi1) * wv2.y);
            }
        }
    }
}

// ---------------------------------------------------------------------------
// General tensor-core GEMM (tf32) with fused epilogue — Wc1' / Wc2.
// MODE 2:BN+ReLU  3:+residual ; concat via Ca.
// ---------------------------------------------------------------------------
template<int MODE>
__global__ void __launch_bounds__(128, 4) gemm_mma(
    const float* __restrict__ W, const float* __restrict__ bias,
    const float* __restrict__ Xa, const float* __restrict__ Xb,
    float* __restrict__ Y, int Cout, int Cin, int Ca,
    const float* __restrict__ e0, const float* __restrict__ e1,
    const float* __restrict__ e2, const float* __restrict__ e3)
{
    extern __shared__ float sg[];
    float* Wb0 = sg;
    float* Wb1 = sg + 64*WG_ST;
    float* Xb0 = sg + 2*64*WG_ST;
    float* Xb1 = Xb0 + 32*XG_ST;

    const int b  = blockIdx.z;
    const int o0 = blockIdx.y * 64;
    const int n0 = blockIdx.x * 128;
    const int t  = threadIdx.x;
    const int lane = t & 31, w = t >> 5;
    const int g = lane >> 2, q4 = lane & 3;
    const int ow = (w & 1) * 32;
    const int nwp = (w >> 1) * 64;
    const int Cb = Cin - Ca;

    auto issue = [&](int i0, int bufi) {
        float* Wd = bufi ? Wb1 : Wb0;
        float* Xd = bufi ? Xb1 : Xb0;
        #pragma unroll
        for (int r = 0; r < 4; r++) {
            int ch = r*128 + t, row = ch >> 3, c4 = (ch & 7) << 2;
            CPA16(s2u(Wd + row*WG_ST + c4), W + (size_t)(o0 + row) * Cin + i0 + c4);
        }
        #pragma unroll
        for (int r = 0; r < 8; r++) {
            int ch = r*128 + t, row = ch >> 5, c4 = (ch & 31) << 2;
            int ig = i0 + row;
            const float* src = (ig < Ca)
                ? Xa + ((size_t)b*Ca + ig) * N_ + n0 + c4
                : Xb + ((size_t)b*Cb + (ig - Ca)) * N_ + n0 + c4;
            CPA16(s2u(Xd + row*XG_ST + c4), src);
        }
        CPA_COMMIT();
    };

    float acc[2][8][4];
    #pragma unroll
    for (int st = 0; st < 2; st++)
        #pragma unroll
        for (int nc = 0; nc < 8; nc++)
            #pragma unroll
            for (int j = 0; j < 4; j++) acc[st][nc][j] = 0.f;

    const int nch = Cin >> 5;
    issue(0, 0);
    for (int i = 0; i < nch; i++) {
        CPA_WAIT0();
        __syncthreads();
        if (i + 1 < nch) issue((i + 1) << 5, (i + 1) & 1);

        const float* Wc = (i & 1) ? Wb1 : Wb0;
        const float* Xc = (i & 1) ? Xb1 : Xb0;

        #pragma unroll
        for (int s = 0; s < 4; s++) {
            uint32_t a2r[2][4];
            #pragma unroll
            for (int st = 0; st < 2; st++) {
                const float* wr0 = &Wc[(ow + 16*st + g    )*WG_ST + 8*s + q4];
                const float* wr1 = &Wc[(ow + 16*st + g + 8)*WG_ST + 8*s + q4];
                a2r[st][0] = __float_as_uint(wr0[0]);
                a2r[st][1] = __float_as_uint(wr1[0]);
                a2r[st][2] = __float_as_uint(wr0[4]);
                a2r[st][3] = __float_as_uint(wr1[4]);
            }
            const float* x0 = &Xc[(8*s + q4    )*XG_ST + nwp + g];
            const float* x1 = &Xc[(8*s + q4 + 4)*XG_ST + nwp + g];
            #pragma unroll
            for (int nc = 0; nc < 8; nc++) {
                uint32_t b0 = __float_as_uint(x0[8*nc]);
                uint32_t b1 = __float_as_uint(x1[8*nc]);
                mma_tf32(acc[0][nc], a2r[0], b0, b1, acc[0][nc]);
                mma_tf32(acc[1][nc], a2r[1], b0, b1, acc[1][nc]);
            }
        }
    }

    #pragma unroll
    for (int st = 0; st < 2; st++) {
        const int row0 = o0 + ow + 16*st + g;
        const int row1 = row0 + 8;
        const float bi0 = bias[row0];
        const float bi1 = bias[row1];
        float inv0, add0, inv1, add1;
        if constexpr (MODE == 2) {
            inv0 = e0[row0] * rsqrtf(e3[row0] + 1e-5f);
            add0 = e1[row0] - e2[row0] * inv0;
            inv1 = e0[row1] * rsqrtf(e3[row1] + 1e-5f);
            add1 = e1[row1] - e2[row1] * inv1;
        }
        const size_t yb0 = ((size_t)b*Cout + row0) * N_;
        const size_t yb1 = ((size_t)b*Cout + row1) * N_;
        #pragma unroll
        for (int nc = 0; nc < 8; nc++) {
            const int n = n0 + nwp + 8*nc + 2*q4;
            float2 y0 = make_float2(acc[st][nc][0] + bi0, acc[st][nc][1] + bi0);
            float2 y1 = make_float2(acc[st][nc][2] + bi1, acc[st][nc][3] + bi1);
            if constexpr (MODE == 2) {
                y0.x = fmaxf(fmaf(y0.x, inv0, add0), 0.f);
                y0.y = fmaxf(fmaf(y0.y, inv0, add0), 0.f);
                y1.x = fmaxf(fmaf(y1.x, inv1, add1), 0.f);
                y1.y = fmaxf(fmaf(y1.y, inv1, add1), 0.f);
            }
            if constexpr (MODE == 3) {
                float2 r0 = *(const float2*)&e0[yb0 + n];
                float2 r1 = *(const float2*)&e0[yb1 + n];
                y0.x += r0.x; y0.y += r0.y;
                y1.x += r1.x; y1.y += r1.y;
            }
            *(float2*)&Y[yb0 + n] = y0;
            *(float2*)&Y[yb1 + n] = y1;
        }
    }
}

// ---------------------------------------------------------------------------
// Attention, bf16 mma, register-resident P, 32 Q-rows per warp (2 strips).
// (unchanged from R14 — passed at ~67us)
// ---------------------------------------------------------------------------
static constexpr int QS_ST = 136;  // u32 (n-tile 128 + pad 8)
static constexpr int KK_ST = 72;   // u32
static constexpr int VP_ST = 36;   // u32
static constexpr int ATT_SMEM = (32*QS_ST + 2*32*KK_ST + 2*64*VP_ST) * 4;  // 54272 B

__global__ void __launch_bounds__(128) attn_bf16(
    const uint32_t* __restrict__ QP, const uint32_t* __restrict__ KP,
    const uint32_t* __restrict__ VP, float* __restrict__ O)
{
    extern __shared__ uint32_t su[];
    uint32_t* Qs  = su;                       // 4352
    uint32_t* Kb0 = su + 4352;
    uint32_t* Kb1 = su + 6656;
    uint32_t* Vb0 = su + 8960;
    uint32_t* Vb1 = su + 11264;

    const int bh = blockIdx.y;
    const int n0 = blockIdx.x * 128;
    const size_t qkb = (size_t)bh * 32 * 2048;
    const size_t vb  = (size_t)bh * 64 * 1024;
    const int t = threadIdx.x;
    const int lane = t & 31, w = t >> 5;
    const int g = lane >> 2, q4 = lane & 3;
    const int nw = w * 32;

    auto issue_kv = [&](int m0, int bufi) {
        uint32_t* Kd = bufi ? Kb1 : Kb0;
        uint32_t* Vd = bufi ? Vb1 : Vb0;
        #pragma unroll
        for (int r = 0; r < 4; r++) {
            int ch = r*128 + t, row = ch >> 4, c4 = (ch & 15) << 2;
            CPA16(s2u(Kd + row*KK_ST + c4), KP + qkb + (size_t)row*2048 + m0 + c4);
        }
        #pragma unroll
        for (int r = 0; r < 4; r++) {
            int ch = r*128 + t, row = ch >> 3, c4 = (ch & 7) << 2;
            CPA16(s2u(Vd + row*VP_ST + c4), VP + vb + (size_t)row*1024 + (m0 >> 1) + c4);
        }
        CPA_COMMIT();
    };

    #pragma unroll
    for (int r = 0; r < 8; r++) {
        int ch = r*128 + t, row = ch >> 5, c4 = (ch & 31) << 2;
        CPA16(s2u(Qs + row*QS_ST + c4), QP + qkb + (size_t)row*2048 + n0 + c4);
    }
    CPA_COMMIT();
    issue_kv(0, 0);
    CPA_WAIT1();
    __syncthreads();

    uint32_t qa[2][4][4];
    #pragma unroll
    for (int st = 0; st < 2; st++) {
        const int nb = nw + 16*st;
        #pragma unroll
        for (int dc = 0; dc < 4; dc++) {
            qa[st][dc][0] = Qs[(8*dc + q4    )*QS_ST + nb + g];
            qa[st][dc][1] = Qs[(8*dc + q4    )*QS_ST + nb + g + 8];
            qa[st][dc][2] = Qs[(8*dc + q4 + 4)*QS_ST + nb + g];
            qa[st][dc][3] = Qs[(8*dc + q4 + 4)*QS_ST + nb + g + 8];
        }
    }

    float o0_[8][4], o1_[8][4];
    #pragma unroll
    for (int dc = 0; dc < 8; dc++)
        #pragma unroll
        for (int j = 0; j < 4; j++) { o0_[dc][j] = 0.f; o1_[dc][j] = 0.f; }
    float l00 = 0.f, l01 = 0.f, l10 = 0.f, l11 = 0.f;

    for (int i = 0; i < M_/64; i++) {
        CPA_WAIT0();
        __syncthreads();
        if (i + 1 < M_/64) issue_kv((i + 1) * 64, (i + 1) & 1);

        const uint32_t* Kc = (i & 1) ? Kb1 : Kb0;
        const uint32_t* Vc = (i & 1) ? Vb1 : Vb0;

        float s0[8][4], s1[8][4];
        #pragma unroll
        for (int mc = 0; mc < 8; mc++)
            #pragma unroll
            for (int j = 0; j < 4; j++) { s0[mc][j] = 0.f; s1[mc][j] = 0.f; }

        #pragma unroll
        for (int dc = 0; dc < 4; dc++) {
            const uint32_t* k0 = &Kc[(8*dc + q4    )*KK_ST + g];
            const uint32_t* k1 = &Kc[(8*dc + q4 + 4)*KK_ST + g];
            #pragma unroll
            for (int mc = 0; mc < 8; mc++) {
                uint32_t b0 = k0[8*mc], b1 = k1[8*mc];
                mma_bf16(s0[mc], qa[0][dc], b0, b1, s0[mc]);
                mma_bf16(s1[mc], qa[1][dc], b0, b1, s1[mc]);
            }
        }

        uint32_t pa0[4][4], pa1[4][4];
        #pragma unroll
        for (int mc = 0; mc < 8; mc++) {
            s0[mc][0] = __expf(s0[mc][0] * 0.125f);
            s0[mc][1] = __expf(s0[mc][1] * 0.125f);
            s0[mc][2] = __expf(s0[mc][2] * 0.125f);
            s0[mc][3] = __expf(s0[mc][3] * 0.125f);
            l00 += s0[mc][0] + s0[mc][1];
            l01 += s0[mc][2] + s0[mc][3];
            s1[mc][0] = __expf(s1[mc][0] * 0.125f);
            s1[mc][1] = __expf(s1[mc][1] * 0.125f);
            s1[mc][2] = __expf(s1[mc][2] * 0.125f);
            s1[mc][3] = __expf(s1[mc][3] * 0.125f);
            l10 += s1[mc][0] + s1[mc][1];
            l11 += s1[mc][2] + s1[mc][3];
        }
        #pragma unroll
        for (int mkc = 0; mkc < 4; mkc++) {
            pa0[mkc][0] = pkbf(s0[2*mkc  ][0], s0[2*mkc  ][1]);
            pa0[mkc][1] = pkbf(s0[2*mkc  ][2], s0[2*mkc  ][3]);
            pa0[mkc][2] = pkbf(s0[2*mkc+1][0], s0[2*mkc+1][1]);
            pa0[mkc][3] = pkbf(s0[2*mkc+1][2], s0[2*mkc+1][3]);
            pa1[mkc][0] = pkbf(s1[2*mkc  ][0], s1[2*mkc  ][1]);
            pa1[mkc][1] = pkbf(s1[2*mkc  ][2], s1[2*mkc  ][3]);
            pa1[mkc][2] = pkbf(s1[2*mkc+1][0], s1[2*mkc+1][1]);
            pa1[mkc][3] = pkbf(s1[2*mkc+1][2], s1[2*mkc+1][3]);
        }

        #pragma unroll
        for (int mkc = 0; mkc < 4; mkc++) {
            #pragma unroll
            for (int dc = 0; dc < 8; dc++) {
                const uint32_t* vr = &Vc[(8*dc + g)*VP_ST + 8*mkc];
                uint32_t v0 = vr[q4], v1 = vr[q4 + 4];
                mma_bf16(o0_[dc], pa0[mkc], v0, v1, o0_[dc]);
                mma_bf16(o1_[dc], pa1[mkc], v0, v1, o1_[dc]);
            }
        }
    }

    l00 += __shfl_xor_sync(0xffffffffu, l00, 1);
    l00 += __shfl_xor_sync(0xffffffffu, l00, 2);
    l01 += __shfl_xor_sync(0xffffffffu, l01, 1);
    l01 += __shfl_xor_sync(0xffffffffu, l01, 2);
    l10 += __shfl_xor_sync(0xffffffffu, l10, 1);
    l10 += __shfl_xor_sync(0xffffffffu, l10, 2);
    l11 += __shfl_xor_sync(0xffffffffu, l11, 1);
    l11 += __shfl_xor_sync(0xffffffffu, l11, 2);
    const float i00 = 1.0f / l00, i01 = 1.0f / l01;
    const float i10 = 1.0f / l10, i11 = 1.0f / l11;

    __syncthreads();
    float* Os = (float*)su;
    #pragma unroll
    for (int dc = 0; dc < 8; dc++) {
        #pragma unroll
        for (int j = 0; j < 2; j++) {
            int d = 8*dc + 2*q4 + j;
            Os[d*QS_ST + nw + g         ] = o0_[dc][j]     * i00;
            Os[d*QS_ST + nw + g + 8     ] = o0_[dc][2 + j] * i01;
            Os[d*QS_ST + nw + 16 + g    ] = o1_[dc][j]     * i10;
            Os[d*QS_ST + nw + 16 + g + 8] = o1_[dc][2 + j] * i11;
        }
    }
    __syncthreads();
    const size_t obase = (size_t)bh * 64 * 2048;
    #pragma unroll
    for (int d = 0; d < 64; d++) {
        O[obase + (size_t)d * 2048 + n0 + t] = Os[d*QS_ST + t];
    }
}

// ---------------------------------------------------------------------------
extern "C" void kernel_launch(void* const* d_in, const int* in_sizes, int n_in,
                              void* d_out, int out_size)
{
    const float* desc1 = (const float*)d_in[0];
    const float* desc2 = (const float*)d_in[1];
    const float* wv    = (const float*)d_in[2];
    const float* Wq    = (const float*)d_in[3];
    const float* bq    = (const float*)d_in[4];
    const float* Wk    = (const float*)d_in[5];
    const float* bk    = (const float*)d_in[6];
    const float* Wv    = (const float*)d_in[7];
    const float* bv    = (const float*)d_in[8];
    const float* Wm    = (const float*)d_in[9];
    const float* bm    = (const float*)d_in[10];
    const float* Wc1   = (const float*)d_in[11];
    const float* bc1   = (const float*)d_in[12];
    const float* gamma = (const float*)d_in[13];
    const float* beta  = (const float*)d_in[14];
    const float* mean  = (const float*)d_in[15];
    const float* var   = (const float*)d_in[16];
    const float* Wc2   = (const float*)d_in[17];
    const float* bc2   = (const float*)d_in[18];
    float* out = (float*)d_out;

    uint32_t *qp, *kp, *vp;
    float *attn, *h, *wf, *bfp;
    cudaGetSymbolAddress((void**)&qp,   g_qp);
    cudaGetSymbolAddress((void**)&kp,   g_kp);
    cudaGetSymbolAddress((void**)&vp,   g_vp);
    cudaGetSymbolAddress((void**)&attn, g_attn);
    cudaGetSymbolAddress((void**)&h,    g_h);
    cudaGetSymbolAddress((void**)&wf,   g_wf);
    cudaGetSymbolAddress((void**)&bfp,  g_bf);

    cudaFuncSetAttribute(gemm_qkv,    cudaFuncAttributeMaxDynamicSharedMemorySize, GEMM_SMEM);
    cudaFuncSetAttribute(gemm_mma<2>, cudaFuncAttributeMaxDynamicSharedMemorySize, GEMM_SMEM);
    cudaFuncSetAttribute(gemm_mma<3>, cudaFuncAttributeMaxDynamicSharedMemorySize, GEMM_SMEM);
    cudaFuncSetAttribute(attn_bf16,   cudaFuncAttributeMaxDynamicSharedMemorySize, ATT_SMEM);

    const dim3 blk(128);

    // Q/K/V projections + Wm-fusion prep (z = 24 slice)
    gemm_qkv<<<dim3(N_/128, C_/64, 25), blk, GEMM_SMEM>>>(
        Wq, bq, Wk, bk, Wv, bv, desc1, desc2, wv, qp, kp, vp,
        Wc1, bc1, Wm, bm, wf, bfp);

    // Attention: n-tile 128, 4 warps x 32 rows
    attn_bf16<<<dim3(N_/128, B_*4), 128, ATT_SMEM>>>(qp, kp, vp, attn);

    const dim3 gp(N_/128, C_/64, B_);
    const dim3 gh(N_/128, 2*C_/64, B_);

    // Fused (Wc1 ∘ [I; Wm]) GEMM + BN + ReLU  — Wm GEMM eliminated
    gemm_mma<2><<<gh, blk, GEMM_SMEM>>>(wf, bfp, desc1, attn, h, 2*C_, 2*C_, C_,
                                        gamma, beta, mean, var);

    // Wc2 + residual
    gemm_mma<3><<<gp, blk, GEMM_SMEM>>>(Wc2, bc2, h, nullptr, out, C_, 2*C_, 2*C_,
                                        desc1, nullptr, nullptr, nullptr);
}

// round 16
// speedup vs baseline: 2.9680x; 1.1049x over previous
#include <cuda_runtime.h>
#include <cuda_bf16.h>
#include <cuda_fp16.h>
#include <math.h>
#include <stdint.h>

static constexpr int B_ = 8;
static constexpr int C_ = 256;
static constexpr int N_ = 2048;
static constexpr int M_ = 2048;

// Scratch (no cudaMalloc allowed) — fp16/bf16 pairs stored as u32
__device__ uint32_t g_d1p[8*128*2048];   // desc1 fp16 (k,k+8)-pairs
__device__ uint32_t g_d2p[8*128*2048];
__device__ uint32_t g_wqp[256*128];      // weights fp16 A-pairs
__device__ uint32_t g_wkp[256*128];
__device__ uint32_t g_wvp[256*128];
__device__ uint32_t g_wc2p[256*256];
__device__ uint32_t g_wfp[512*256];      // fused Wc1' fp16 pairs
__device__ uint32_t g_wc1bp[512*128];    // Wc1[:,256:] A-pairs (prep GEMM)
__device__ uint32_t g_wmp[128*256];      // Wm B-pairs
__device__ float    g_bfv[512];          // fused bias
__device__ uint32_t g_qp[B_*4*32*2048];  // bf16 attention operands (unchanged)
__device__ uint32_t g_kp[B_*4*32*2048];
__device__ uint32_t g_vp[B_*4*64*1024];
__device__ uint32_t g_attp[8*128*2048];  // attention out, fp16 pairs
__device__ uint32_t g_hp[8*256*2048];    // h, fp16 pairs

// ---------------------------------------------------------------------------
// helpers
// ---------------------------------------------------------------------------
__device__ __forceinline__ uint32_t s2u(const void* p) {
    return (uint32_t)__cvta_generic_to_shared(p);
}
#define CPA16(dst, src) \
    asm volatile("cp.async.cg.shared.global [%0], [%1], 16;" :: "r"(dst), "l"(src))
#define CPA_COMMIT() asm volatile("cp.async.commit_group;")
#define CPA_WAIT0()  asm volatile("cp.async.wait_group 0;")
#define CPA_WAIT1()  asm volatile("cp.async.wait_group 1;")

__device__ __forceinline__ void mma_bf16(
    float d[4], const uint32_t a[4], uint32_t b0, uint32_t b1, const float c[4])
{
    asm volatile(
        "mma.sync.aligned.m16n8k16.row.col.f32.bf16.bf16.f32 "
        "{%0,%1,%2,%3}, {%4,%5,%6,%7}, {%8,%9}, {%10,%11,%12,%13};"
        : "=f"(d[0]), "=f"(d[1]), "=f"(d[2]), "=f"(d[3])
        : "r"(a[0]), "r"(a[1]), "r"(a[2]), "r"(a[3]),
          "r"(b0), "r"(b1),
          "f"(c[0]), "f"(c[1]), "f"(c[2]), "f"(c[3]));
}
__device__ __forceinline__ void mma_f16(
    float d[4], const uint32_t a[4], uint32_t b0, uint32_t b1, const float c[4])
{
    asm volatile(
        "mma.sync.aligned.m16n8k16.row.col.f32.f16.f16.f32 "
        "{%0,%1,%2,%3}, {%4,%5,%6,%7}, {%8,%9}, {%10,%11,%12,%13};"
        : "=f"(d[0]), "=f"(d[1]), "=f"(d[2]), "=f"(d[3])
        : "r"(a[0]), "r"(a[1]), "r"(a[2]), "r"(a[3]),
          "r"(b0), "r"(b1),
          "f"(c[0]), "f"(c[1]), "f"(c[2]), "f"(c[3]));
}
__device__ __forceinline__ uint32_t pkbf(float lo, float hi) {
    __nv_bfloat162 h = __floats2bfloat162_rn(lo, hi);
    return *(uint32_t*)&h;
}
__device__ __forceinline__ uint32_t pkhf(float lo, float hi) {
    __half2 h = __floats2half2_rn(lo, hi);
    return *(uint32_t*)&h;
}

// ---------------------------------------------------------------------------
// Pre-pass: fp16 pair-pack conversions + fused bias.
// Pair convention everywhere: kp -> k = 16*(kp>>3) + (kp&7), pair (k, k+8).
// ---------------------------------------------------------------------------
__global__ void __launch_bounds__(256) prepass(
    const float* __restrict__ desc1, const float* __restrict__ desc2,
    const float* __restrict__ Wq, const float* __restrict__ Wk,
    const float* __restrict__ Wv, const float* __restrict__ Wc2,
    const float* __restrict__ Wc1, const float* __restrict__ Wm,
    const float* __restrict__ bm, const float* __restrict__ bc1,
    uint32_t* __restrict__ d1p, uint32_t* __restrict__ d2p,
    uint32_t* __restrict__ wqp, uint32_t* __restrict__ wkp,
    uint32_t* __restrict__ wvp, uint32_t* __restrict__ wc2p,
    uint32_t* __restrict__ wfp, uint32_t* __restrict__ wc1bp,
    uint32_t* __restrict__ wmp, float* __restrict__ bfv)
{
    int x = blockIdx.x;
    const int t = threadIdx.x;

    if (x < 2048) {  // desc1 / desc2 rows
        const float* src = (x < 1024) ? desc1 : desc2;
        uint32_t* dst = (x < 1024) ? d1p : d2p;
        int xi = x & 1023;
        int b = xi >> 7, kp = xi & 127;
        int k = 16*(kp>>3) + (kp&7);
        const float* r0 = src + ((size_t)b*256 + k) * 2048;
        const float* r1 = r0 + 8*2048;
        uint32_t* o = dst + ((size_t)b*128 + kp) * 2048;
        for (int c = t*4; c < 2048; c += 1024) {
            float4 a  = *(const float4*)&r0[c];
            float4 bb = *(const float4*)&r1[c];
            *(uint4*)&o[c] = make_uint4(pkhf(a.x,bb.x), pkhf(a.y,bb.y),
                                        pkhf(a.z,bb.z), pkhf(a.w,bb.w));
        }
        return;
    }
    x -= 2048;
    if (x < 768) {  // Wq/Wk/Wv rows (Kd=256)
        const float* W = (x < 256) ? Wq : (x < 512) ? Wk : Wv;
        uint32_t* o    = (x < 256) ? wqp : (x < 512) ? wkp : wvp;
        int row = x & 255;
        for (int kp = t; kp < 128; kp += 256) {
            int k = 16*(kp>>3) + (kp&7);
            o[row*128 + kp] = pkhf(W[row*256 + k], W[row*256 + k + 8]);
        }
        return;
    }
    x -= 768;
    if (x < 256) {  // Wc2 rows (Kd=512)
        for (int kp = t; kp < 256; kp += 256) {
            int k = 16*(kp>>3) + (kp&7);
            wc2p[x*256 + kp] = pkhf(Wc2[x*512 + k], Wc2[x*512 + k + 8]);
        }
        return;
    }
    x -= 256;
    if (x < 512) {  // Wc1a -> Wf[:, 0:128]
        for (int kp = t; kp < 128; kp += 256) {
            int k = 16*(kp>>3) + (kp&7);
            wfp[x*256 + kp] = pkhf(Wc1[x*512 + k], Wc1[x*512 + k + 8]);
        }
        return;
    }
    x -= 512;
    if (x < 512) {  // Wc1b A-pairs
        for (int kp = t; kp < 128; kp += 256) {
            int k = 16*(kp>>3) + (kp&7);
            wc1bp[x*128 + kp] = pkhf(Wc1[x*512 + 256 + k], Wc1[x*512 + 256 + k + 8]);
        }
        return;
    }
    x -= 512;
    if (x < 128) {  // Wm B-pairs: wmp[kp][i]
        int k = 16*(x>>3) + (x&7);
        for (int i = t; i < 256; i += 256)
            wmp[x*256 + i] = pkhf(Wm[k*256 + i], Wm[(k+8)*256 + i]);
        return;
    }
    x -= 128;
    if (x < 2) {  // bf = bc1 + Wc1b @ bm (fp32)
        int row = x*256 + t;
        float s = 0.f;
        const float* wr = Wc1 + (size_t)row*512 + 256;
        #pragma unroll 4
        for (int j = 0; j < 256; j++) s += wr[j] * bm[j];
        bfv[row] = bc1[row] + s;
    }
}

// ---------------------------------------------------------------------------
// fp16 GEMM tile geometry: 64 o x 128 n, chunk 32 k (16 pair-rows), 2-stage.
// Wp smem [64][20] u32 (A banks 20g+q4: distinct), Xp smem [16][136] (8q4+g).
// ---------------------------------------------------------------------------
static constexpr int WP_ST = 20;
static constexpr int XP_ST = 136;
static constexpr int GEMM_SMEM_H = (2*64*WP_ST + 2*16*XP_ST) * 4;  // 27648 B

// ---------------------------------------------------------------------------
// Fused Q/K/V projection (fp16 mainloop) + Wf2 prep GEMM (z == 24).
// ---------------------------------------------------------------------------
__global__ void __launch_bounds__(128, 4) gemm_qkv(
    const uint32_t* __restrict__ wqp, const float* __restrict__ bq,
    const uint32_t* __restrict__ wkp, const float* __restrict__ bk,
    const uint32_t* __restrict__ wvp, const float* __restrict__ bv,
    const uint32_t* __restrict__ d1p, const uint32_t* __restrict__ d2p,
    const float* __restrict__ wv,
    uint32_t* __restrict__ qp, uint32_t* __restrict__ kp, uint32_t* __restrict__ vp,
    const uint32_t* __restrict__ wc1bp, const uint32_t* __restrict__ wmp,
    uint32_t* __restrict__ wfp)
{
    extern __shared__ uint32_t sgu[];
    uint32_t* Wb0 = sgu;
    uint32_t* Wb1 = sgu + 64*WP_ST;
    uint32_t* Xb0 = sgu + 2*64*WP_ST;
    uint32_t* Xb1 = Xb0 + 16*XP_ST;

    const int t  = threadIdx.x;
    const int lane = t & 31, w = t >> 5;
    const int g = lane >> 2, q4 = lane & 3;
    const int ow = (w & 1) * 32;
    const int nwp = (w >> 1) * 64;

    float acc[2][8][4];
    #pragma unroll
    for (int st = 0; st < 2; st++)
        #pragma unroll
        for (int nc = 0; nc < 8; nc++)
            #pragma unroll
            for (int j = 0; j < 4; j++) acc[st][nc][j] = 0.f;

    // ======================= PREP SLICE (z == 24) =======================
    if (blockIdx.z == 24) {
        const int cid = blockIdx.y * gridDim.x + blockIdx.x;
        if (cid >= 16) return;
        const int o0 = (cid >> 1) * 64;
        const int i0 = (cid & 1) * 128;

        auto issueP = [&](int c0, int bufi) {
            uint32_t* Wd = bufi ? Wb1 : Wb0;
            uint32_t* Xd = bufi ? Xb1 : Xb0;
            #pragma unroll
            for (int r = 0; r < 2; r++) {
                int ch = r*128 + t, row = ch >> 2, q = (ch & 3) << 2;
                CPA16(s2u(Wd + row*WP_ST + q), wc1bp + (size_t)(o0+row)*128 + c0 + q);
            }
            #pragma unroll
            for (int r = 0; r < 4; r++) {
                int ch = r*128 + t, row = ch >> 5, c4 = (ch & 31) << 2;
                CPA16(s2u(Xd + row*XP_ST + c4), wmp + (size_t)(c0+row)*256 + i0 + c4);
            }
            CPA_COMMIT();
        };

        issueP(0, 0);
        for (int i = 0; i < 8; i++) {
            CPA_WAIT0();
            __syncthreads();
            if (i + 1 < 8) issueP((i + 1) * 16, (i + 1) & 1);
            const uint32_t* Wc = (i & 1) ? Wb1 : Wb0;
            const uint32_t* Xc = (i & 1) ? Xb1 : Xb0;
            #pragma unroll
            for (int dc = 0; dc < 2; dc++) {
                uint32_t a2r[2][4];
                #pragma unroll
                for (int st = 0; st < 2; st++) {
                    const uint32_t* wr0 = &Wc[(ow + 16*st + g    )*WP_ST + 8*dc + q4];
                    const uint32_t* wr1 = &Wc[(ow + 16*st + g + 8)*WP_ST + 8*dc + q4];
                    a2r[st][0] = wr0[0]; a2r[st][1] = wr1[0];
                    a2r[st][2] = wr0[4]; a2r[st][3] = wr1[4];
                }
                const uint32_t* x0 = &Xc[(8*dc + q4    )*XP_ST + nwp + g];
                const uint32_t* x1 = &Xc[(8*dc + q4 + 4)*XP_ST + nwp + g];
                #pragma unroll
                for (int nc = 0; nc < 8; nc++) {
                    uint32_t b0 = x0[8*nc], b1 = x1[8*nc];
                    mma_f16(acc[0][nc], a2r[0], b0, b1, acc[0][nc]);
                    mma_f16(acc[1][nc], a2r[1], b0, b1, acc[1][nc]);
                }
            }
        }
        // pairs along output n: (n, n+8) -> Wf[:, 128 + kpc]
        #pragma unroll
        for (int st = 0; st < 2; st++) {
            const int row0 = o0 + ow + 16*st + g;
            const int row1 = row0 + 8;
            #pragma unroll
            for (int nc = 0; nc < 8; nc += 2) {
                const int n = i0 + nwp + 8*nc + 2*q4;
                const int kpc = 128 + ((n >> 4) << 3) + (n & 7);
                wfp[(size_t)row0*256 + kpc    ] = pkhf(acc[st][nc][0], acc[st][nc+1][0]);
                wfp[(size_t)row0*256 + kpc + 1] = pkhf(acc[st][nc][1], acc[st][nc+1][1]);
                wfp[(size_t)row1*256 + kpc    ] = pkhf(acc[st][nc][2], acc[st][nc+1][2]);
                wfp[(size_t)row1*256 + kpc + 1] = pkhf(acc[st][nc][3], acc[st][nc+1][3]);
            }
        }
        return;
    }

    // ======================= Q/K/V PROJECTIONS =======================
    const int p  = blockIdx.z >> 3;
    const int b  = blockIdx.z & 7;
    const uint32_t* W    = (p == 0) ? wqp : (p == 1) ? wkp : wvp;
    const float* bias    = (p == 0) ? bq : (p == 1) ? bk : bv;
    const uint32_t* X    = ((p == 0) ? d1p : d2p) + (size_t)b*128*2048;
    uint32_t* Yp         = (p == 0) ? qp : (p == 1) ? kp : vp;

    const int o0 = blockIdx.y * 64;
    const int n0 = blockIdx.x * 128;

    auto issue = [&](int c0, int bufi) {
        uint32_t* Wd = bufi ? Wb1 : Wb0;
        uint32_t* Xd = bufi ? Xb1 : Xb0;
        #pragma unroll
        for (int r = 0; r < 2; r++) {
            int ch = r*128 + t, row = ch >> 2, q = (ch & 3) << 2;
            CPA16(s2u(Wd + row*WP_ST + q), W + (size_t)(o0+row)*128 + c0 + q);
        }
        #pragma unroll
        for (int r = 0; r < 4; r++) {
            int ch = r*128 + t, row = ch >> 5, c4 = (ch & 31) << 2;
            CPA16(s2u(Xd + row*XP_ST + c4), X + (size_t)(c0+row)*2048 + n0 + c4);
        }
        CPA_COMMIT();
    };

    issue(0, 0);
    for (int i = 0; i < 8; i++) {
        CPA_WAIT0();
        __syncthreads();
        if (i + 1 < 8) issue((i + 1) * 16, (i + 1) & 1);
        const uint32_t* Wc = (i & 1) ? Wb1 : Wb0;
        const uint32_t* Xc = (i & 1) ? Xb1 : Xb0;
        #pragma unroll
        for (int dc = 0; dc < 2; dc++) {
            uint32_t a2r[2][4];
            #pragma unroll
            for (int st = 0; st < 2; st++) {
                const uint32_t* wr0 = &Wc[(ow + 16*st + g    )*WP_ST + 8*dc + q4];
                const uint32_t* wr1 = &Wc[(ow + 16*st + g + 8)*WP_ST + 8*dc + q4];
                a2r[st][0] = wr0[0]; a2r[st][1] = wr1[0];
                a2r[st][2] = wr0[4]; a2r[st][3] = wr1[4];
            }
            const uint32_t* x0 = &Xc[(8*dc + q4    )*XP_ST + nwp + g];
            const uint32_t* x1 = &Xc[(8*dc + q4 + 4)*XP_ST + nwp + g];
            #pragma unroll
            for (int nc = 0; nc < 8; nc++) {
                uint32_t b0 = x0[8*nc], b1 = x1[8*nc];
                mma_f16(acc[0][nc], a2r[0], b0, b1, acc[0][nc]);
                mma_f16(acc[1][nc], a2r[1], b0, b1, acc[1][nc]);
            }
        }
    }

    // ---- Epilogue: bf16 pack for attention (unchanged mapping) ----
    #pragma unroll
    for (int st = 0; st < 2; st++) {
        const int row0 = o0 + ow + 16*st + g;
        const int row1 = row0 + 8;
        const float bi0 = bias[row0];
        const float bi1 = bias[row1];
        const int d0 = row0 & 63, h = row0 >> 6;

        if (p < 2) {
            const size_t obase =
                (((size_t)b*4 + h)*32 + ((d0 >> 4)*8 + (d0 & 7))) * (size_t)N_;
            #pragma unroll
            for (int nc = 0; nc < 8; nc++) {
                const int n = n0 + nwp + 8*nc + 2*q4;
                Yp[obase + n    ] = pkbf(acc[st][nc][0] + bi0, acc[st][nc][2] + bi1);
                Yp[obase + n + 1] = pkbf(acc[st][nc][1] + bi0, acc[st][nc][3] + bi1);
            }
        } else {
            const size_t b0v = (((size_t)b*4 + h)*64 + d0    ) * (size_t)(N_/2);
            const size_t b1v = (((size_t)b*4 + h)*64 + d0 + 8) * (size_t)(N_/2);
            #pragma unroll
            for (int nc = 0; nc < 8; nc++) {
                const int n = n0 + nwp + 8*nc + 2*q4;
                float2 wv2 = *(const float2*)&wv[(size_t)b * N_ + n];
                Yp[b0v + (n >> 1)] = pkbf((acc[st][nc][0] + bi0) * wv2.x,
                                          (acc[st][nc][1] + bi0) * wv2.y);
                Yp[b1v + (n >> 1)] = pkbf((acc[st][nc][2] + bi1) * wv2.x,
                                          (acc[st][nc][3] + bi1) * wv2.y);
            }
        }
    }
}

// ---------------------------------------------------------------------------
// fp16 GEMM with fused epilogue.
// MODE 2: BN+ReLU, write fp16 pairs to Hp.   MODE 3: +residual, write fp32 Y.
// Kp = pair-K (Cin/2); X concat: pair-row < Cap from Xa else Xb (per batch).
// ---------------------------------------------------------------------------
template<int MODE>
__global__ void __launch_bounds__(128, 4) gemm_h(
    const uint32_t* __restrict__ Wp, const float* __restrict__ bias,
    const uint32_t* __restrict__ Xa, const uint32_t* __restrict__ Xb,
    float* __restrict__ Y, uint32_t* __restrict__ Hp,
    int Cout, int Kp, int Cap,
    const float* __restrict__ e0, const float* __restrict__ e1,
    const float* __restrict__ e2, const float* __restrict__ e3)
{
    extern __shared__ uint32_t sgu[];
    uint32_t* Wb0 = sgu;
    uint32_t* Wb1 = sgu + 64*WP_ST;
    uint32_t* Xb0 = sgu + 2*64*WP_ST;
    uint32_t* Xb1 = Xb0 + 16*XP_ST;

    const int b  = blockIdx.z;
    const int o0 = blockIdx.y * 64;
    const int n0 = blockIdx.x * 128;
    const int t  = threadIdx.x;
    const int lane = t & 31, w = t >> 5;
    const int g = lane >> 2, q4 = lane & 3;
    const int ow = (w & 1) * 32;
    const int nwp = (w >> 1) * 64;

    const uint32_t* XaB = Xa + (size_t)b * Cap * 2048;
    const uint32_t* XbB = Xb + (size_t)b * (Kp - Cap) * 2048;

    auto issue = [&](int c0, int bufi) {
        uint32_t* Wd = bufi ? Wb1 : Wb0;
        uint32_t* Xd = bufi ? Xb1 : Xb0;
        #pragma unroll
        for (int r = 0; r < 2; r++) {
            int ch = r*128 + t, row = ch >> 2, q = (ch & 3) << 2;
            CPA16(s2u(Wd + row*WP_ST + q), Wp + (size_t)(o0+row)*Kp + c0 + q);
        }
        #pragma unroll
        for (int r = 0; r < 4; r++) {
            int ch = r*128 + t, row = ch >> 5, c4 = (ch & 31) << 2;
            int ig = c0 + row;
            const uint32_t* src = (ig < Cap)
                ? XaB + (size_t)ig * 2048 + n0 + c4
                : XbB + (size_t)(ig - Cap) * 2048 + n0 + c4;
            CPA16(s2u(Xd + row*XP_ST + c4), src);
        }
        CPA_COMMIT();
    };

    float acc[2][8][4];
    #pragma unroll
    for (int st = 0; st < 2; st++)
        #pragma unroll
        for (int nc = 0; nc < 8; nc++)
            #pragma unroll
            for (int j = 0; j < 4; j++) acc[st][nc][j] = 0.f;

    const int nch = Kp >> 4;
    issue(0, 0);
    for (int i = 0; i < nch; i++) {
        CPA_WAIT0();
        __syncthreads();
        if (i + 1 < nch) issue((i + 1) * 16, (i + 1) & 1);
        const uint32_t* Wc = (i & 1) ? Wb1 : Wb0;
        const uint32_t* Xc = (i & 1) ? Xb1 : Xb0;
        #pragma unroll
        for (int dc = 0; dc < 2; dc++) {
            uint32_t a2r[2][4];
            #pragma unroll
            for (int st = 0; st < 2; st++) {
                const uint32_t* wr0 = &Wc[(ow + 16*st + g    )*WP_ST + 8*dc + q4];
                const uint32_t* wr1 = &Wc[(ow + 16*st + g + 8)*WP_ST + 8*dc + q4];
                a2r[st][0] = wr0[0]; a2r[st][1] = wr1[0];
                a2r[st][2] = wr0[4]; a2r[st][3] = wr1[4];
            }
            const uint32_t* x0 = &Xc[(8*dc + q4    )*XP_ST + nwp + g];
            const uint32_t* x1 = &Xc[(8*dc + q4 + 4)*XP_ST + nwp + g];
            #pragma unroll
            for (int nc = 0; nc < 8; nc++) {
                uint32_t b0 = x0[8*nc], b1 = x1[8*nc];
                mma_f16(acc[0][nc], a2r[0], b0, b1, acc[0][nc]);
                mma_f16(acc[1][nc], a2r[1], b0, b1, acc[1][nc]);
            }
        }
    }

    #pragma unroll
    for (int st = 0; st < 2; st++) {
        const int row0 = o0 + ow + 16*st + g;
        const int row1 = row0 + 8;
        const float bi0 = bias[row0];
        const float bi1 = bias[row1];

        if constexpr (MODE == 2) {
            float inv0 = e0[row0] * rsqrtf(e3[row0] + 1e-5f);
            float add0 = e1[row0] - e2[row0] * inv0;
            float inv1 = e0[row1] * rsqrtf(e3[row1] + 1e-5f);
            float add1 = e1[row1] - e2[row1] * inv1;
            const int kpo = ((row0 >> 4) << 3) + g;     // pair (row0,row1)
            uint32_t* orow = Hp + ((size_t)b*(Cout>>1) + kpo) * 2048;
            #pragma unroll
            for (int nc = 0; nc < 8; nc++) {
                const int n = n0 + nwp + 8*nc + 2*q4;
                float y0x = fmaxf(fmaf(acc[st][nc][0] + bi0, inv0, add0), 0.f);
                float y0y = fmaxf(fmaf(acc[st][nc][1] + bi0, inv0, add0), 0.f);
                float y1x = fmaxf(fmaf(acc[st][nc][2] + bi1, inv1, add1), 0.f);
                float y1y = fmaxf(fmaf(acc[st][nc][3] + bi1, inv1, add1), 0.f);
                *(uint2*)&orow[n] = make_uint2(pkhf(y0x, y1x), pkhf(y0y, y1y));
            }
        } else {
            const size_t yb0 = ((size_t)b*Cout + row0) * N_;
            const size_t yb1 = ((size_t)b*Cout + row1) * N_;
            #pragma unroll
            for (int nc = 0; nc < 8; nc++) {
                const int n = n0 + nwp + 8*nc + 2*q4;
                float2 y0 = make_float2(acc[st][nc][0] + bi0, acc[st][nc][1] + bi0);
                float2 y1 = make_float2(acc[st][nc][2] + bi1, acc[st][nc][3] + bi1);
                float2 r0 = *(const float2*)&e0[yb0 + n];
                float2 r1 = *(const float2*)&e0[yb1 + n];
                y0.x += r0.x; y0.y += r0.y;
                y1.x += r1.x; y1.y += r1.y;
                *(float2*)&Y[yb0 + n] = y0;
                *(float2*)&Y[yb1 + n] = y1;
            }
        }
    }
}

// ---------------------------------------------------------------------------
// Attention, bf16 mma, register-resident P, 2 strips/warp (proven R14 core);
// output now written as fp16 (c, c+8)-pairs into attp.
// ---------------------------------------------------------------------------
static constexpr int QS_ST = 136;  // u32
static constexpr int KK_ST = 72;   // u32
static constexpr int VP_ST = 36;   // u32
static constexpr int ATT_SMEM = (32*QS_ST + 2*32*KK_ST + 2*64*VP_ST) * 4;  // 54272 B

__global__ void __launch_bounds__(128) attn_bf16(
    const uint32_t* __restrict__ QP, const uint32_t* __restrict__ KP,
    const uint32_t* __restrict__ VP, uint32_t* __restrict__ ATT)
{
    extern __shared__ uint32_t su[];
    uint32_t* Qs  = su;
    uint32_t* Kb0 = su + 4352;
    uint32_t* Kb1 = su + 6656;
    uint32_t* Vb0 = su + 8960;
    uint32_t* Vb1 = su + 11264;

    const int bh = blockIdx.y;
    const int n0 = blockIdx.x * 128;
    const size_t qkb = (size_t)bh * 32 * 2048;
    const size_t vb  = (size_t)bh * 64 * 1024;
    const int t = threadIdx.x;
    const int lane = t & 31, w = t >> 5;
    const int g = lane >> 2, q4 = lane & 3;
    const int nw = w * 32;

    auto issue_kv = [&](int m0, int bufi) {
        uint32_t* Kd = bufi ? Kb1 : Kb0;
        uint32_t* Vd = bufi ? Vb1 : Vb0;
        #pragma unroll
        for (int r = 0; r < 4; r++) {
            int ch = r*128 + t, row = ch >> 4, c4 = (ch & 15) << 2;
            CPA16(s2u(Kd + row*KK_ST + c4), KP + qkb + (size_t)row*2048 + m0 + c4);
        }
        #pragma unroll
        for (int r = 0; r < 4; r++) {
            int ch = r*128 + t, row = ch >> 3, c4 = (ch & 7) << 2;
            CPA16(s2u(Vd + row*VP_ST + c4), VP + vb + (size_t)row*1024 + (m0 >> 1) + c4);
        }
        CPA_COMMIT();
    };

    #pragma unroll
    for (int r = 0; r < 8; r++) {
        int ch = r*128 + t, row = ch >> 5, c4 = (ch & 31) << 2;
        CPA16(s2u(Qs + row*QS_ST + c4), QP + qkb + (size_t)row*2048 + n0 + c4);
    }
    CPA_COMMIT();
    issue_kv(0, 0);
    CPA_WAIT1();
    __syncthreads();

    uint32_t qa[2][4][4];
    #pragma unroll
    for (int st = 0; st < 2; st++) {
        const int nb = nw + 16*st;
        #pragma unroll
        for (int dc = 0; dc < 4; dc++) {
            qa[st][dc][0] = Qs[(8*dc + q4    )*QS_ST + nb + g];
            qa[st][dc][1] = Qs[(8*dc + q4    )*QS_ST + nb + g + 8];
            qa[st][dc][2] = Qs[(8*dc + q4 + 4)*QS_ST + nb + g];
            qa[st][dc][3] = Qs[(8*dc + q4 + 4)*QS_ST + nb + g + 8];
        }
    }

    float o0_[8][4], o1_[8][4];
    #pragma unroll
    for (int dc = 0; dc < 8; dc++)
        #pragma unroll
        for (int j = 0; j < 4; j++) { o0_[dc][j] = 0.f; o1_[dc][j] = 0.f; }
    float l00 = 0.f, l01 = 0.f, l10 = 0.f, l11 = 0.f;

    for (int i = 0; i < M_/64; i++) {
        CPA_WAIT0();
        __syncthreads();
        if (i + 1 < M_/64) issue_kv((i + 1) * 64, (i + 1) & 1);

        const uint32_t* Kc = (i & 1) ? Kb1 : Kb0;
        const uint32_t* Vc = (i & 1) ? Vb1 : Vb0;

        float s0[8][4], s1[8][4];
        #pragma unroll
        for (int mc = 0; mc < 8; mc++)
            #pragma unroll
            for (int j = 0; j < 4; j++) { s0[mc][j] = 0.f; s1[mc][j] = 0.f; }

        #pragma unroll
        for (int dc = 0; dc < 4; dc++) {
            const uint32_t* k0 = &Kc[(8*dc + q4    )*KK_ST + g];
            const uint32_t* k1 = &Kc[(8*dc + q4 + 4)*KK_ST + g];
            #pragma unroll
            for (int mc = 0; mc < 8; mc++) {
                uint32_t b0 = k0[8*mc], b1 = k1[8*mc];
                mma_bf16(s0[mc], qa[0][dc], b0, b1, s0[mc]);
                mma_bf16(s1[mc], qa[1][dc], b0, b1, s1[mc]);
            }
        }

        uint32_t pa0[4][4], pa1[4][4];
        #pragma unroll
        for (int mc = 0; mc < 8; mc++) {
            s0[mc][0] = __expf(s0[mc][0] * 0.125f);
            s0[mc][1] = __expf(s0[mc][1] * 0.125f);
            s0[mc][2] = __expf(s0[mc][2] * 0.125f);
            s0[mc][3] = __expf(s0[mc][3] * 0.125f);
            l00 += s0[mc][0] + s0[mc][1];
            l01 += s0[mc][2] + s0[mc][3];
            s1[mc][0] = __expf(s1[mc][0] * 0.125f);
            s1[mc][1] = __expf(s1[mc][1] * 0.125f);
            s1[mc][2] = __expf(s1[mc][2] * 0.125f);
            s1[mc][3] = __expf(s1[mc][3] * 0.125f);
            l10 += s1[mc][0] + s1[mc][1];
            l11 += s1[mc][2] + s1[mc][3];
        }
        #pragma unroll
        for (int mkc = 0; mkc < 4; mkc++) {
            pa0[mkc][0] = pkbf(s0[2*mkc  ][0], s0[2*mkc  ][1]);
            pa0[mkc][1] = pkbf(s0[2*mkc  ][2], s0[2*mkc  ][3]);
            pa0[mkc][2] = pkbf(s0[2*mkc+1][0], s0[2*mkc+1][1]);
            pa0[mkc][3] = pkbf(s0[2*mkc+1][2], s0[2*mkc+1][3]);
            pa1[mkc][0] = pkbf(s1[2*mkc  ][0], s1[2*mkc  ][1]);
            pa1[mkc][1] = pkbf(s1[2*mkc  ][2], s1[2*mkc  ][3]);
            pa1[mkc][2] = pkbf(s1[2*mkc+1][0], s1[2*mkc+1][1]);
            pa1[mkc][3] = pkbf(s1[2*mkc+1][2], s1[2*mkc+1][3]);
        }

        #pragma unroll
        for (int mkc = 0; mkc < 4; mkc++) {
            #pragma unroll
            for (int dc = 0; dc < 8; dc++) {
                const uint32_t* vr = &Vc[(8*dc + g)*VP_ST + 8*mkc];
                uint32_t v0 = vr[q4], v1 = vr[q4 + 4];
                mma_bf16(o0_[dc], pa0[mkc], v0, v1, o0_[dc]);
                mma_bf16(o1_[dc], pa1[mkc], v0, v1, o1_[dc]);
            }
        }
    }

    l00 += __shfl_xor_sync(0xffffffffu, l00, 1);
    l00 += __shfl_xor_sync(0xffffffffu, l00, 2);
    l01 += __shfl_xor_sync(0xffffffffu, l01, 1);
    l01 += __shfl_xor_sync(0xffffffffu, l01, 2);
    l10 += __shfl_xor_sync(0xffffffffu, l10, 1);
    l10 += __shfl_xor_sync(0xffffffffu, l10, 2);
    l11 += __shfl_xor_sync(0xffffffffu, l11, 1);
    l11 += __shfl_xor_sync(0xffffffffu, l11, 2);
    const float i00 = 1.0f / l00, i01 = 1.0f / l01;
    const float i10 = 1.0f / l10, i11 = 1.0f / l11;

    __syncthreads();
    float* Os = (float*)su;
    #pragma unroll
    for (int dc = 0; dc < 8; dc++) {
        #pragma unroll
        for (int j = 0; j < 2; j++) {
            int d = 8*dc + 2*q4 + j;
            Os[d*QS_ST + nw + g         ] = o0_[dc][j]     * i00;
            Os[d*QS_ST + nw + g + 8     ] = o0_[dc][2 + j] * i01;
            Os[d*QS_ST + nw + 16 + g    ] = o1_[dc][j]     * i10;
            Os[d*QS_ST + nw + 16 + g + 8] = o1_[dc][2 + j] * i11;
        }
    }
    __syncthreads();
    // fp16 pair output: pair rows 32 per head
    const int bb = bh >> 2, hh = bh & 3;
    uint32_t* arow = ATT + ((size_t)bb*128 + 32*hh) * 2048 + n0;
    #pragma unroll
    for (int r = 0; r < 32; r++) {
        int d = 16*(r >> 3) + (r & 7);
        arow[(size_t)r * 2048 + t] = pkhf(Os[d*QS_ST + t], Os[(d+8)*QS_ST + t]);
    }
}

// ---------------------------------------------------------------------------
extern "C" void kernel_launch(void* const* d_in, const int* in_sizes, int n_in,
                              void* d_out, int out_size)
{
    const float* desc1 = (const float*)d_in[0];
    const float* desc2 = (const float*)d_in[1];
    const float* wv    = (const float*)d_in[2];
    const float* Wq    = (const float*)d_in[3];
    const float* bq    = (const float*)d_in[4];
    const float* Wk    = (const float*)d_in[5];
    const float* bk    = (const float*)d_in[6];
    const float* Wv    = (const float*)d_in[7];
    const float* bv    = (const float*)d_in[8];
    const float* Wm    = (const float*)d_in[9];
    const float* bm    = (const float*)d_in[10];
    const float* Wc1   = (const float*)d_in[11];
    const float* bc1   = (const float*)d_in[12];
    const float* gamma = (const float*)d_in[13];
    const float* beta  = (const float*)d_in[14];
    const float* mean  = (const float*)d_in[15];
    const float* var   = (const float*)d_in[16];
    const float* Wc2   = (const float*)d_in[17];
    const float* bc2   = (const float*)d_in[18];
    float* out = (float*)d_out;

    uint32_t *d1p, *d2p, *wqp, *wkp, *wvp, *wc2p, *wfp, *wc1bp, *wmp;
    uint32_t *qp, *kp, *vp, *attp, *hp;
    float *bfv;
    cudaGetSymbolAddress((void**)&d1p,   g_d1p);
    cudaGetSymbolAddress((void**)&d2p,   g_d2p);
    cudaGetSymbolAddress((void**)&wqp,   g_wqp);
    cudaGetSymbolAddress((void**)&wkp,   g_wkp);
    cudaGetSymbolAddress((void**)&wvp,   g_wvp);
    cudaGetSymbolAddress((void**)&wc2p,  g_wc2p);
    cudaGetSymbolAddress((void**)&wfp,   g_wfp);
    cudaGetSymbolAddress((void**)&wc1bp, g_wc1bp);
    cudaGetSymbolAddress((void**)&wmp,   g_wmp);
    cudaGetSymbolAddress((void**)&bfv,   g_bfv);
    cudaGetSymbolAddress((void**)&qp,    g_qp);
    cudaGetSymbolAddress((void**)&kp,    g_kp);
    cudaGetSymbolAddress((void**)&vp,    g_vp);
    cudaGetSymbolAddress((void**)&attp,  g_attp);
    cudaGetSymbolAddress((void**)&hp,    g_hp);

    cudaFuncSetAttribute(gemm_qkv,  cudaFuncAttributeMaxDynamicSharedMemorySize, GEMM_SMEM_H);
    cudaFuncSetAttribute(gemm_h<2>, cudaFuncAttributeMaxDynamicSharedMemorySize, GEMM_SMEM_H);
    cudaFuncSetAttribute(gemm_h<3>, cudaFuncAttributeMaxDynamicSharedMemorySize, GEMM_SMEM_H);
    cudaFuncSetAttribute(attn_bf16, cudaFuncAttributeMaxDynamicSharedMemorySize, ATT_SMEM);

    // 0) fp16 pair-pack conversions + fused bias
    prepass<<<4226, 256>>>(desc1, desc2, Wq, Wk, Wv, Wc2, Wc1, Wm, bm, bc1,
                           d1p, d2p, wqp, wkp, wvp, wc2p, wfp, wc1bp, wmp, bfv);

    // 1) Q/K/V projections (fp16) + Wf2 prep GEMM (z = 24)
    gemm_qkv<<<dim3(N_/128, C_/64, 25), 128, GEMM_SMEM_H>>>(
        wqp, bq, wkp, bk, wvp, bv, d1p, d2p, wv, qp, kp, vp, wc1bp, wmp, wfp);

    // 2) attention (bf16), fp16-pair output
    attn_bf16<<<dim3(N_/128, B_*4), 128, ATT_SMEM>>>(qp, kp, vp, attp);

    // 3) fused (Wc1 ∘ [I; Wm]) + BN + ReLU -> h (fp16 pairs)
    gemm_h<2><<<dim3(N_/128, 8, B_), 128, GEMM_SMEM_H>>>(
        wfp, bfv, d1p, attp, nullptr, hp, 2*C_, 256, 128,
        gamma, beta, mean, var);

    // 4) Wc2 + residual -> out (fp32)
    gemm_h<3><<<dim3(N_/128, 4, B_), 128, GEMM_SMEM_H>>>(
        wc2p, bc2, hp, hp, out, nullptr, C_, 256, 256,
        desc1, nullptr, nullptr, nullptr);
}